// round 2
// baseline (speedup 1.0000x reference)
#include <cuda_runtime.h>
#include <math.h>

// ---------------- scratch (no allocs allowed) ----------------
__device__ float g_ho[52428800];    // (b,h,t,d)  210 MB
__device__ float g_z1[104857600];   // (b,h,f,t)  419 MB
__device__ float g_z2[52428800];    // (b,h,g,t)  210 MB
__device__ float g_mean1[512], g_istd1[512];
__device__ float g_mean2[256], g_istd2[256];

// ---------------- kernel A shared layout ----------------
struct SmemA {
    float ss[200 * 68];    // seq rows -> s rows (padded stride 68)
    float kk[200 * 20];    // k rows (padded stride 20)
    float vv[200 * 20];
    float qs[200 * 20];
    float wq[1024], wk[1024], wv[1024];
    float wo[1024];        // [j][i] = W_o[h,j,i]
    float w1[4096];        // [f][d]
    float w2t[4096];       // [f][j] transposed ffn_w2
    float weff[8192];      // folded mw1 [f][d]
    float c1b[128];
    float te[64], lngs[64], lnbs[64], b1s[64], b2s[64];
};
constexpr int SMEM_A_BYTES = (int)sizeof(SmemA);   // 186112 B

__global__ void __launch_bounds__(256) kA(
    const float* __restrict__ seq, const float* __restrict__ targ,
    const float* __restrict__ Wqkv, const float* __restrict__ Wo,
    const float* __restrict__ lng, const float* __restrict__ lnb,
    const float* __restrict__ fw1, const float* __restrict__ fb1,
    const float* __restrict__ fw2, const float* __restrict__ fb2,
    const float* __restrict__ mw1, const float* __restrict__ mb1)
{
    extern __shared__ float smraw[];
    SmemA* s = reinterpret_cast<SmemA*>(smraw);
    const int tid = threadIdx.x;
    const int bid = blockIdx.x;
    const int b = bid >> 2, h = bid & 3;

    // ---- cooperative loads (coalesced) ----
    for (int i = tid; i < 12800; i += 256)
        s->ss[(i >> 6) * 68 + (i & 63)] = seq[(size_t)b * 12800 + i];
    for (int i = tid; i < 1024; i += 256) {
        int r = i >> 6, d = i & 63;
        s->wq[i] = Wqkv[(h * 16 + r) * 64 + d];
        s->wk[i] = Wqkv[(64 + h * 16 + r) * 64 + d];
        s->wv[i] = Wqkv[(128 + h * 16 + r) * 64 + d];
        s->wo[i] = Wo[h * 1024 + i];
    }
    for (int i = tid; i < 4096; i += 256) {
        s->w1[i] = fw1[h * 4096 + i];
        int f = i >> 6, j = i & 63;
        s->w2t[i] = fw2[h * 4096 + j * 64 + f];
    }
    if (tid < 64) {
        s->te[tid]   = targ[b * 64 + tid];
        s->lngs[tid] = lng[h * 64 + tid];
        s->lnbs[tid] = lnb[h * 64 + tid];
        s->b1s[tid]  = fb1[h * 64 + tid];
        s->b2s[tid]  = fb2[h * 64 + tid];
    }
    __syncthreads();

    // ---- fold mw1 -> Weff, c1  (din affine in head_out) ----
    const float* m1h = mw1 + (size_t)h * 128 * 256;
    for (int i = tid; i < 8192; i += 256) {
        int f = i >> 6, d = i & 63;
        const float* r = m1h + f * 256;
        s->weff[i] = r[64 + d] - r[128 + d] + s->te[d] * r[192 + d];
    }
    if (tid < 128) {
        const float* r = m1h + tid * 256;
        float a = mb1[h * 128 + tid];
        #pragma unroll 4
        for (int d = 0; d < 64; d++) a = fmaf(s->te[d], r[d] + r[128 + d], a);
        s->c1b[tid] = a;
    }
    __syncthreads();

    const bool act = tid < 200;
    const int t = act ? tid : 0;
    const int t68 = t * 68, t20 = t * 20;

    // ---- QKV (thread = token) ----
    if (act) {
        float4 x[16];
        #pragma unroll
        for (int j4 = 0; j4 < 16; j4++) x[j4] = *(const float4*)&s->ss[t68 + j4 * 4];
        for (int i = 0; i < 16; i++) {
            const float4* wqp = (const float4*)&s->wq[i * 64];
            const float4* wkp = (const float4*)&s->wk[i * 64];
            const float4* wvp = (const float4*)&s->wv[i * 64];
            float q0=0,q1=0,q2=0,q3=0,k0=0,k1=0,k2=0,k3=0,v0=0,v1=0,v2=0,v3=0;
            #pragma unroll
            for (int j4 = 0; j4 < 16; j4++) {
                float4 xv = x[j4];
                float4 w = wqp[j4];
                q0=fmaf(xv.x,w.x,q0); q1=fmaf(xv.y,w.y,q1); q2=fmaf(xv.z,w.z,q2); q3=fmaf(xv.w,w.w,q3);
                w = wkp[j4];
                k0=fmaf(xv.x,w.x,k0); k1=fmaf(xv.y,w.y,k1); k2=fmaf(xv.z,w.z,k2); k3=fmaf(xv.w,w.w,k3);
                w = wvp[j4];
                v0=fmaf(xv.x,w.x,v0); v1=fmaf(xv.y,w.y,v1); v2=fmaf(xv.z,w.z,v2); v3=fmaf(xv.w,w.w,v3);
            }
            s->qs[t20 + i] = (q0+q1)+(q2+q3);
            s->kk[t20 + i] = (k0+k1)+(k2+k3);
            s->vv[t20 + i] = (v0+v1)+(v2+v3);
        }
    }
    __syncthreads();
    if (!act) return;

    // ---- attention (exp without max: scores bounded ~O(1)) ----
    float4 qa = *(const float4*)&s->qs[t20];
    float4 qb = *(const float4*)&s->qs[t20 + 4];
    float4 qc = *(const float4*)&s->qs[t20 + 8];
    float4 qd = *(const float4*)&s->qs[t20 + 12];
    float4 cA = make_float4(0,0,0,0), cB = cA, cC = cA, cD = cA;
    float l = 0.f;
    #pragma unroll 2
    for (int t2 = 0; t2 < 200; t2++) {
        const float4* kp = (const float4*)&s->kk[t2 * 20];
        float4 k0 = kp[0], k1 = kp[1], k2 = kp[2], k3 = kp[3];
        float d0 = fmaf(qa.x,k0.x, fmaf(qa.y,k0.y, fmaf(qa.z,k0.z, qa.w*k0.w)));
        float d1 = fmaf(qb.x,k1.x, fmaf(qb.y,k1.y, fmaf(qb.z,k1.z, qb.w*k1.w)));
        float d2 = fmaf(qc.x,k2.x, fmaf(qc.y,k2.y, fmaf(qc.z,k2.z, qc.w*k2.w)));
        float d3 = fmaf(qd.x,k3.x, fmaf(qd.y,k3.y, fmaf(qd.z,k3.z, qd.w*k3.w)));
        float p = __expf(((d0+d1)+(d2+d3)) * 0.25f);
        l += p;
        const float4* vp = (const float4*)&s->vv[t2 * 20];
        float4 v0 = vp[0], v1 = vp[1], v2 = vp[2], v3 = vp[3];
        cA.x=fmaf(p,v0.x,cA.x); cA.y=fmaf(p,v0.y,cA.y); cA.z=fmaf(p,v0.z,cA.z); cA.w=fmaf(p,v0.w,cA.w);
        cB.x=fmaf(p,v1.x,cB.x); cB.y=fmaf(p,v1.y,cB.y); cB.z=fmaf(p,v1.z,cB.z); cB.w=fmaf(p,v1.w,cB.w);
        cC.x=fmaf(p,v2.x,cC.x); cC.y=fmaf(p,v2.y,cC.y); cC.z=fmaf(p,v2.z,cC.z); cC.w=fmaf(p,v2.w,cC.w);
        cD.x=fmaf(p,v3.x,cD.x); cD.y=fmaf(p,v3.y,cD.y); cD.z=fmaf(p,v3.z,cD.z); cD.w=fmaf(p,v3.w,cD.w);
    }
    float rl = 1.f / l;
    cA.x*=rl; cA.y*=rl; cA.z*=rl; cA.w*=rl;
    cB.x*=rl; cB.y*=rl; cB.z*=rl; cB.w*=rl;
    cC.x*=rl; cC.y*=rl; cC.z*=rl; cC.w*=rl;
    cD.x*=rl; cD.y*=rl; cD.z*=rl; cD.w*=rl;

    // ---- W_o + residual, LN stats (pass 1) ----
    float mu = 0.f, q2s = 0.f;
    for (int j = 0; j < 64; j++) {
        const float4* wr = (const float4*)&s->wo[j * 16];
        float4 w0 = wr[0], w1r = wr[1], w2r = wr[2], w3r = wr[3];
        float a0 = fmaf(cA.x,w0.x, fmaf(cA.y,w0.y, fmaf(cA.z,w0.z, cA.w*w0.w)));
        float a1 = fmaf(cB.x,w1r.x, fmaf(cB.y,w1r.y, fmaf(cB.z,w1r.z, cB.w*w1r.w)));
        float a2 = fmaf(cC.x,w2r.x, fmaf(cC.y,w2r.y, fmaf(cC.z,w2r.z, cC.w*w2r.w)));
        float a3 = fmaf(cD.x,w3r.x, fmaf(cD.y,w3r.y, fmaf(cD.z,w3r.z, cD.w*w3r.w)));
        float sj = (a0+a1)+(a2+a3) + s->ss[t68 + j];
        s->ss[t68 + j] = sj;
        mu += sj;
        q2s = fmaf(sj, sj, q2s);
    }
    mu *= (1.f / 64.f);
    float var = q2s * (1.f / 64.f) - mu * mu;
    float rstd = rsqrtf(var + 1e-5f);

    // ---- LN pass 2 -> sreg ----
    float4 sreg[16];
    #pragma unroll
    for (int j4 = 0; j4 < 16; j4++) {
        float4 sv = *(const float4*)&s->ss[t68 + j4 * 4];
        float4 g  = *(const float4*)&s->lngs[j4 * 4];
        float4 bb = *(const float4*)&s->lnbs[j4 * 4];
        sreg[j4].x = fmaf((sv.x - mu) * rstd, g.x, bb.x);
        sreg[j4].y = fmaf((sv.y - mu) * rstd, g.y, bb.y);
        sreg[j4].z = fmaf((sv.z - mu) * rstd, g.z, bb.z);
        sreg[j4].w = fmaf((sv.w - mu) * rstd, g.w, bb.w);
    }

    // ---- FFN fused (ho = s + b2 + W2^T relu(W1 s + b1)) ----
    float4 ho[16];
    #pragma unroll
    for (int j4 = 0; j4 < 16; j4++) {
        float4 bv = *(const float4*)&s->b2s[j4 * 4];
        ho[j4].x = sreg[j4].x + bv.x;
        ho[j4].y = sreg[j4].y + bv.y;
        ho[j4].z = sreg[j4].z + bv.z;
        ho[j4].w = sreg[j4].w + bv.w;
    }
    for (int f = 0; f < 64; f++) {
        const float4* w1p = (const float4*)&s->w1[f * 64];
        float a0=0,a1=0,a2=0,a3=0;
        #pragma unroll
        for (int j4 = 0; j4 < 16; j4++) {
            float4 w = w1p[j4];
            float4 sv = sreg[j4];
            a0=fmaf(sv.x,w.x,a0); a1=fmaf(sv.y,w.y,a1); a2=fmaf(sv.z,w.z,a2); a3=fmaf(sv.w,w.w,a3);
        }
        float hf = fmaxf((a0+a1)+(a2+a3) + s->b1s[f], 0.f);
        const float4* w2p = (const float4*)&s->w2t[f * 64];
        #pragma unroll
        for (int j4 = 0; j4 < 16; j4++) {
            float4 w = w2p[j4];
            ho[j4].x=fmaf(hf,w.x,ho[j4].x); ho[j4].y=fmaf(hf,w.y,ho[j4].y);
            ho[j4].z=fmaf(hf,w.z,ho[j4].z); ho[j4].w=fmaf(hf,w.w,ho[j4].w);
        }
    }

    // ---- store head_out ----
    float4* hop = (float4*)(g_ho + ((size_t)bid * 200 + t) * 64);
    #pragma unroll
    for (int j4 = 0; j4 < 16; j4++) hop[j4] = ho[j4];

    // ---- z1 via folded Weff (coalesced (f,t) stores) ----
    float* z1p = g_z1 + (size_t)bid * 25600 + t;
    #pragma unroll 2
    for (int f = 0; f < 128; f++) {
        const float4* wp = (const float4*)&s->weff[f * 64];
        float a0=0,a1=0,a2=0,a3=0;
        #pragma unroll
        for (int j4 = 0; j4 < 16; j4++) {
            float4 w = wp[j4];
            float4 hv = ho[j4];
            a0=fmaf(hv.x,w.x,a0); a1=fmaf(hv.y,w.y,a1); a2=fmaf(hv.z,w.z,a2); a3=fmaf(hv.w,w.w,a3);
        }
        z1p[f * 200] = (a0+a1)+(a2+a3) + s->c1b[f];
    }
}

// ---------------- stats kernels (1 block per (h,f), double accum) ----------------
__global__ void __launch_bounds__(256) kStats1()
{
    const int j = blockIdx.x;          // h*128+f
    const int h = j >> 7, f = j & 127;
    const int tid = threadIdx.x;
    double sm = 0.0, sq = 0.0;
    #pragma unroll 4
    for (int b = 0; b < 1024; b++) {
        const float* p = g_z1 + ((size_t)(b * 4 + h) * 128 + f) * 200;
        for (int t = tid; t < 200; t += 256) {
            double v = (double)p[t];
            sm += v; sq += v * v;
        }
    }
    __shared__ double rs[256], rq[256];
    rs[tid] = sm; rq[tid] = sq;
    __syncthreads();
    for (int o = 128; o > 0; o >>= 1) {
        if (tid < o) { rs[tid] += rs[tid + o]; rq[tid] += rq[tid + o]; }
        __syncthreads();
    }
    if (tid == 0) {
        double N = 204800.0;
        double mean = rs[0] / N;
        double var = rq[0] / N - mean * mean;
        if (var < 0.0) var = 0.0;
        g_mean1[j] = (float)mean;
        g_istd1[j] = (float)(1.0 / sqrt(var + 1e-9));
    }
}

__global__ void __launch_bounds__(256) kStats2()
{
    const int j = blockIdx.x;          // h*64+g
    const int h = j >> 6, f = j & 63;
    const int tid = threadIdx.x;
    double sm = 0.0, sq = 0.0;
    #pragma unroll 4
    for (int b = 0; b < 1024; b++) {
        const float* p = g_z2 + ((size_t)(b * 4 + h) * 64 + f) * 200;
        for (int t = tid; t < 200; t += 256) {
            double v = (double)p[t];
            sm += v; sq += v * v;
        }
    }
    __shared__ double rs[256], rq[256];
    rs[tid] = sm; rq[tid] = sq;
    __syncthreads();
    for (int o = 128; o > 0; o >>= 1) {
        if (tid < o) { rs[tid] += rs[tid + o]; rq[tid] += rq[tid + o]; }
        __syncthreads();
    }
    if (tid == 0) {
        double N = 204800.0;
        double mean = rs[0] / N;
        double var = rq[0] / N - mean * mean;
        if (var < 0.0) var = 0.0;
        g_mean2[j] = (float)mean;
        g_istd2[j] = (float)(1.0 / sqrt(var + 1e-9));
    }
}

// ---------------- kernel C: dice1 + mw2 GEMM ----------------
__global__ void __launch_bounds__(256) kC(
    const float* __restrict__ mw2, const float* __restrict__ mb2,
    const float* __restrict__ alpha1)
{
    __shared__ float w2ts[8192];       // [f][g] transposed mw2
    __shared__ float mn[128], isd[128], al[128], mb[64];
    const int tid = threadIdx.x, bid = blockIdx.x, h = bid & 3;
    for (int i = tid; i < 8192; i += 256) {
        int f = i >> 6, g = i & 63;
        w2ts[i] = mw2[(size_t)h * 8192 + g * 128 + f];
    }
    if (tid < 128) {
        int j = h * 128 + tid;
        mn[tid] = g_mean1[j]; isd[tid] = g_istd1[j]; al[tid] = alpha1[j];
    }
    if (tid < 64) mb[tid] = mb2[h * 64 + tid];
    __syncthreads();
    if (tid >= 200) return;

    const float* zp = g_z1 + (size_t)bid * 25600 + tid;
    float4 acc[16];
    #pragma unroll
    for (int g4 = 0; g4 < 16; g4++) acc[g4] = make_float4(0,0,0,0);

    #pragma unroll 2
    for (int f = 0; f < 128; f++) {
        float zv = zp[f * 200];
        float xa = (zv - mn[f]) * isd[f];
        float p = __fdividef(1.f, 1.f + __expf(-xa));
        float xv = (p + al[f] * (1.f - p)) * zv;
        const float4* wp = (const float4*)&w2ts[f * 64];
        #pragma unroll
        for (int g4 = 0; g4 < 16; g4++) {
            float4 w = wp[g4];
            acc[g4].x=fmaf(xv,w.x,acc[g4].x); acc[g4].y=fmaf(xv,w.y,acc[g4].y);
            acc[g4].z=fmaf(xv,w.z,acc[g4].z); acc[g4].w=fmaf(xv,w.w,acc[g4].w);
        }
    }
    float* op = g_z2 + (size_t)bid * 12800 + tid;
    #pragma unroll
    for (int g4 = 0; g4 < 16; g4++) {
        int g = g4 * 4;
        op[(g+0)*200] = acc[g4].x + mb[g+0];
        op[(g+1)*200] = acc[g4].y + mb[g+1];
        op[(g+2)*200] = acc[g4].z + mb[g+2];
        op[(g+3)*200] = acc[g4].w + mb[g+3];
    }
}

// ---------------- kernel E: dice2 + score + softmax + pooling ----------------
__global__ void __launch_bounds__(256) kE(
    const int* __restrict__ mask, const float* __restrict__ mw3,
    const float* __restrict__ mb3, const float* __restrict__ alpha2,
    float* __restrict__ out)
{
    __shared__ float w3s[64], m2s[64], i2s[64], a2s[64];
    __shared__ float red[256];
    __shared__ float wts[200];
    const int tid = threadIdx.x, bid = blockIdx.x;
    const int b = bid >> 2, h = bid & 3;
    if (tid < 64) {
        int j = h * 64 + tid;
        w3s[tid] = mw3[j]; m2s[tid] = g_mean2[j]; i2s[tid] = g_istd2[j]; a2s[tid] = alpha2[j];
    }
    __syncthreads();

    float sc = -3.0e38f;
    if (tid < 200) {
        const float* zp = g_z2 + (size_t)bid * 12800 + tid;
        float a = 0.f;
        #pragma unroll 4
        for (int g = 0; g < 64; g++) {
            float zv = zp[g * 200];
            float xa = (zv - m2s[g]) * i2s[g];
            float p = __fdividef(1.f, 1.f + __expf(-xa));
            float xv = (p + a2s[g] * (1.f - p)) * zv;
            a = fmaf(xv, w3s[g], a);
        }
        sc = a + mb3[h];
        if (mask[b * 200 + tid] == 0) sc = -1e9f;
    }
    red[tid] = sc;
    __syncthreads();
    for (int o = 128; o > 0; o >>= 1) {
        if (tid < o) red[tid] = fmaxf(red[tid], red[tid + o]);
        __syncthreads();
    }
    float mx = red[0];
    __syncthreads();
    float e = (tid < 200) ? __expf(sc - mx) : 0.f;
    red[tid] = e;
    __syncthreads();
    for (int o = 128; o > 0; o >>= 1) {
        if (tid < o) red[tid] += red[tid + o];
        __syncthreads();
    }
    float inv = 1.f / red[0];
    if (tid < 200) wts[tid] = e * inv;
    __syncthreads();

    // pooling: thread = (chunk c, dim d)
    const int c = tid >> 6, d = tid & 63;
    const float* hp = g_ho + (size_t)bid * 12800 + d;
    float acc = 0.f;
    #pragma unroll 2
    for (int t2 = c * 50; t2 < c * 50 + 50; t2++)
        acc = fmaf(wts[t2], hp[t2 * 64], acc);
    red[tid] = acc;
    __syncthreads();
    if (tid < 64)
        out[(size_t)bid * 64 + tid] = (red[tid] + red[tid + 64]) + (red[tid + 128] + red[tid + 192]);
}

// ---------------- launch ----------------
extern "C" void kernel_launch(void* const* d_in, const int* in_sizes, int n_in,
                              void* d_out, int out_size)
{
    const float* seq  = (const float*)d_in[0];
    const float* targ = (const float*)d_in[1];
    const int*   mask = (const int*)d_in[2];
    const float* Wqkv = (const float*)d_in[3];
    const float* Wo   = (const float*)d_in[4];
    const float* lng  = (const float*)d_in[5];
    const float* lnb  = (const float*)d_in[6];
    const float* fw1  = (const float*)d_in[7];
    const float* fb1  = (const float*)d_in[8];
    const float* fw2  = (const float*)d_in[9];
    const float* fb2  = (const float*)d_in[10];
    const float* mw1  = (const float*)d_in[11];
    const float* mb1  = (const float*)d_in[12];
    const float* a1   = (const float*)d_in[13];
    const float* mw2  = (const float*)d_in[14];
    const float* mb2  = (const float*)d_in[15];
    const float* a2   = (const float*)d_in[16];
    const float* mw3  = (const float*)d_in[17];
    const float* mb3  = (const float*)d_in[18];
    float* out = (float*)d_out;

    cudaFuncSetAttribute(kA, cudaFuncAttributeMaxDynamicSharedMemorySize, SMEM_A_BYTES);
    kA<<<4096, 256, SMEM_A_BYTES>>>(seq, targ, Wqkv, Wo, lng, lnb,
                                    fw1, fb1, fw2, fb2, mw1, mb1);
    kStats1<<<512, 256>>>();
    kC<<<4096, 256>>>(mw2, mb2, a1);
    kStats2<<<256, 256>>>();
    kE<<<4096, 256>>>(mask, mw3, mb3, a2, out);
}

// round 3
// speedup vs baseline: 1.1683x; 1.1683x over previous
#include <cuda_runtime.h>
#include <math.h>

typedef unsigned long long u64;

// ---------------- f32x2 packed helpers ----------------
__device__ __forceinline__ u64 fma2(u64 a, u64 b, u64 c) {
    u64 d; asm("fma.rn.f32x2 %0, %1, %2, %3;" : "=l"(d) : "l"(a), "l"(b), "l"(c)); return d;
}
__device__ __forceinline__ u64 pack2(float x, float y) {
    u64 r; asm("mov.b64 %0, {%1, %2};" : "=l"(r) : "f"(x), "f"(y)); return r;
}
__device__ __forceinline__ float hsum2(u64 v) {
    float a, b; asm("mov.b64 {%0, %1}, %2;" : "=f"(a), "=f"(b) : "l"(v)); return a + b;
}
union F4U { float4 f; u64 u[2]; };
__device__ __forceinline__ void ld2x(const float* p, u64& a, u64& b) {
    F4U t; t.f = *(const float4*)p; a = t.u[0]; b = t.u[1];
}

// ---------------- scratch (no allocs allowed) ----------------
__device__ float g_ho[52428800];    // (b,h,t,d)  210 MB
__device__ float g_z1[104857600];   // (b,h,f,t)  419 MB
__device__ float g_z2[52428800];    // (b,h,g,t)  210 MB
__device__ double g_p1[4096 * 2];   // stage-1 partials (512 j x 8 slices)
__device__ double g_p2[2048 * 2];   // (256 j x 8 slices)
__device__ float g_mean1[512], g_istd1[512];
__device__ float g_mean2[256], g_istd2[256];

// ---------------- kernel A shared layout ----------------
struct SmemA {
    float ss[200 * 68];    // seq rows -> s rows (padded stride 68)
    float kk[200 * 20];
    float vv[200 * 20];
    float qs[200 * 20];
    float wq[1024], wk[1024], wv[1024];
    float wo[1024];
    float w1[4096];        // [f][d]
    float w2t[4096];       // [f][j] transposed ffn_w2
    float weff[8192];      // folded mw1 [f][d]
    float c1b[128];
    float te[64], lngs[64], lnbs[64], b1s[64], b2s[64];
};
constexpr int SMEM_A_BYTES = (int)sizeof(SmemA);

__global__ void __launch_bounds__(256) kA(
    const float* __restrict__ seq, const float* __restrict__ targ,
    const float* __restrict__ Wqkv, const float* __restrict__ Wo,
    const float* __restrict__ lng, const float* __restrict__ lnb,
    const float* __restrict__ fw1, const float* __restrict__ fb1,
    const float* __restrict__ fw2, const float* __restrict__ fb2,
    const float* __restrict__ mw1, const float* __restrict__ mb1)
{
    extern __shared__ float smraw[];
    SmemA* s = reinterpret_cast<SmemA*>(smraw);
    const int tid = threadIdx.x;
    const int bid = blockIdx.x;
    const int b = bid >> 2, h = bid & 3;

    // ---- cooperative loads ----
    for (int i = tid; i < 12800; i += 256)
        s->ss[(i >> 6) * 68 + (i & 63)] = seq[(size_t)b * 12800 + i];
    for (int i = tid; i < 1024; i += 256) {
        int r = i >> 6, d = i & 63;
        s->wq[i] = Wqkv[(h * 16 + r) * 64 + d];
        s->wk[i] = Wqkv[(64 + h * 16 + r) * 64 + d];
        s->wv[i] = Wqkv[(128 + h * 16 + r) * 64 + d];
        s->wo[i] = Wo[h * 1024 + i];
    }
    for (int i = tid; i < 4096; i += 256) {
        s->w1[i] = fw1[h * 4096 + i];
        int f = i >> 6, j = i & 63;
        s->w2t[i] = fw2[h * 4096 + j * 64 + f];
    }
    if (tid < 64) {
        s->te[tid]   = targ[b * 64 + tid];
        s->lngs[tid] = lng[h * 64 + tid];
        s->lnbs[tid] = lnb[h * 64 + tid];
        s->b1s[tid]  = fb1[h * 64 + tid];
        s->b2s[tid]  = fb2[h * 64 + tid];
    }
    __syncthreads();

    // ---- fold mw1 -> Weff, c1 ----
    const float* m1h = mw1 + (size_t)h * 128 * 256;
    for (int i = tid; i < 8192; i += 256) {
        int f = i >> 6, d = i & 63;
        const float* r = m1h + f * 256;
        s->weff[i] = r[64 + d] - r[128 + d] + s->te[d] * r[192 + d];
    }
    if (tid < 128) {
        const float* r = m1h + tid * 256;
        float a = mb1[h * 128 + tid];
        #pragma unroll 4
        for (int d = 0; d < 64; d++) a = fmaf(s->te[d], r[d] + r[128 + d], a);
        s->c1b[tid] = a;
    }
    __syncthreads();

    const bool act = tid < 200;
    const int t = act ? tid : 0;
    const int t68 = t * 68, t20 = t * 20;

    // ---- QKV (thread = token), f32x2 ----
    if (act) {
        u64 xp[32];
        #pragma unroll
        for (int j4 = 0; j4 < 16; j4++) ld2x(&s->ss[t68 + j4 * 4], xp[2 * j4], xp[2 * j4 + 1]);
        #pragma unroll 4
        for (int i = 0; i < 16; i++) {
            u64 q0 = 0, q1 = 0, k0 = 0, k1 = 0, v0 = 0, v1 = 0, wa, wb;
            #pragma unroll
            for (int j4 = 0; j4 < 16; j4++) {
                ld2x(&s->wq[i * 64 + j4 * 4], wa, wb);
                q0 = fma2(xp[2 * j4], wa, q0); q1 = fma2(xp[2 * j4 + 1], wb, q1);
                ld2x(&s->wk[i * 64 + j4 * 4], wa, wb);
                k0 = fma2(xp[2 * j4], wa, k0); k1 = fma2(xp[2 * j4 + 1], wb, k1);
                ld2x(&s->wv[i * 64 + j4 * 4], wa, wb);
                v0 = fma2(xp[2 * j4], wa, v0); v1 = fma2(xp[2 * j4 + 1], wb, v1);
            }
            s->qs[t20 + i] = hsum2(q0) + hsum2(q1);
            s->kk[t20 + i] = hsum2(k0) + hsum2(k1);
            s->vv[t20 + i] = hsum2(v0) + hsum2(v1);
        }
    }
    __syncthreads();
    if (!act) return;

    // ---- attention (exp without max: scores bounded) ----
    u64 qp[8];
    #pragma unroll
    for (int r = 0; r < 4; r++) ld2x(&s->qs[t20 + r * 4], qp[2 * r], qp[2 * r + 1]);
    u64 ctx[8];
    #pragma unroll
    for (int r = 0; r < 8; r++) ctx[r] = 0ull;
    float l = 0.f;
    #pragma unroll 2
    for (int t2 = 0; t2 < 200; t2++) {
        const float* kr = &s->kk[t2 * 20];
        u64 d0 = 0, d1 = 0, ka, kb;
        ld2x(kr,      ka, kb); d0 = fma2(qp[0], ka, d0); d1 = fma2(qp[1], kb, d1);
        ld2x(kr + 4,  ka, kb); d0 = fma2(qp[2], ka, d0); d1 = fma2(qp[3], kb, d1);
        ld2x(kr + 8,  ka, kb); d0 = fma2(qp[4], ka, d0); d1 = fma2(qp[5], kb, d1);
        ld2x(kr + 12, ka, kb); d0 = fma2(qp[6], ka, d0); d1 = fma2(qp[7], kb, d1);
        float p = __expf((hsum2(d0) + hsum2(d1)) * 0.25f);
        l += p;
        u64 pp = pack2(p, p);
        const float* vr = &s->vv[t2 * 20];
        u64 va, vb;
        ld2x(vr,      va, vb); ctx[0] = fma2(pp, va, ctx[0]); ctx[1] = fma2(pp, vb, ctx[1]);
        ld2x(vr + 4,  va, vb); ctx[2] = fma2(pp, va, ctx[2]); ctx[3] = fma2(pp, vb, ctx[3]);
        ld2x(vr + 8,  va, vb); ctx[4] = fma2(pp, va, ctx[4]); ctx[5] = fma2(pp, vb, ctx[5]);
        ld2x(vr + 12, va, vb); ctx[6] = fma2(pp, va, ctx[6]); ctx[7] = fma2(pp, vb, ctx[7]);
    }
    {
        float rl = 1.f / l;
        u64 rl2 = pack2(rl, rl);
        #pragma unroll
        for (int r = 0; r < 8; r++) ctx[r] = fma2(ctx[r], rl2, 0ull);
    }

    // ---- W_o + residual, LN stats ----
    float mu = 0.f, q2s = 0.f;
    #pragma unroll 4
    for (int j = 0; j < 64; j++) {
        const float* wr = &s->wo[j * 16];
        u64 a0 = 0, a1 = 0, wa, wb;
        ld2x(wr,      wa, wb); a0 = fma2(ctx[0], wa, a0); a1 = fma2(ctx[1], wb, a1);
        ld2x(wr + 4,  wa, wb); a0 = fma2(ctx[2], wa, a0); a1 = fma2(ctx[3], wb, a1);
        ld2x(wr + 8,  wa, wb); a0 = fma2(ctx[4], wa, a0); a1 = fma2(ctx[5], wb, a1);
        ld2x(wr + 12, wa, wb); a0 = fma2(ctx[6], wa, a0); a1 = fma2(ctx[7], wb, a1);
        float sj = hsum2(a0) + hsum2(a1) + s->ss[t68 + j];
        s->ss[t68 + j] = sj;
        mu += sj;
        q2s = fmaf(sj, sj, q2s);
    }
    mu *= (1.f / 64.f);
    float var = q2s * (1.f / 64.f) - mu * mu;
    float rstd = rsqrtf(var + 1e-5f);

    // ---- LN pass 2 -> srg ; ho = srg + b2 ----
    u64 srg[32], ho[32];
    {
        u64 rstd2 = pack2(rstd, rstd);
        float nm = -mu * rstd;
        u64 nmr = pack2(nm, nm);
        u64 one2 = pack2(1.f, 1.f);
        #pragma unroll
        for (int j4 = 0; j4 < 16; j4++) {
            u64 sa, sb, ga, gb, ba, bb, ca, cb;
            ld2x(&s->ss[t68 + j4 * 4], sa, sb);
            ld2x(&s->lngs[j4 * 4], ga, gb);
            ld2x(&s->lnbs[j4 * 4], ba, bb);
            u64 na = fma2(sa, rstd2, nmr);
            u64 nb = fma2(sb, rstd2, nmr);
            srg[2 * j4]     = fma2(na, ga, ba);
            srg[2 * j4 + 1] = fma2(nb, gb, bb);
            ld2x(&s->b2s[j4 * 4], ca, cb);
            ho[2 * j4]     = fma2(srg[2 * j4], one2, ca);
            ho[2 * j4 + 1] = fma2(srg[2 * j4 + 1], one2, cb);
        }
    }

    // ---- FFN fused ----
    #pragma unroll 2
    for (int f = 0; f < 64; f++) {
        const float* w1r = &s->w1[f * 64];
        u64 a0 = 0, a1 = 0, a2 = 0, a3 = 0, wa, wb;
        #pragma unroll
        for (int j4 = 0; j4 < 16; j4 += 2) {
            ld2x(&w1r[j4 * 4], wa, wb);
            a0 = fma2(srg[2 * j4], wa, a0); a1 = fma2(srg[2 * j4 + 1], wb, a1);
            ld2x(&w1r[j4 * 4 + 4], wa, wb);
            a2 = fma2(srg[2 * j4 + 2], wa, a2); a3 = fma2(srg[2 * j4 + 3], wb, a3);
        }
        float hf = fmaxf((hsum2(a0) + hsum2(a1)) + (hsum2(a2) + hsum2(a3)) + s->b1s[f], 0.f);
        u64 hf2 = pack2(hf, hf);
        const float* w2r = &s->w2t[f * 64];
        #pragma unroll
        for (int j4 = 0; j4 < 16; j4++) {
            ld2x(&w2r[j4 * 4], wa, wb);
            ho[2 * j4]     = fma2(hf2, wa, ho[2 * j4]);
            ho[2 * j4 + 1] = fma2(hf2, wb, ho[2 * j4 + 1]);
        }
    }

    // ---- store head_out ----
    float4* hop = (float4*)(g_ho + ((size_t)bid * 200 + t) * 64);
    #pragma unroll
    for (int j4 = 0; j4 < 16; j4++) {
        F4U tmp; tmp.u[0] = ho[2 * j4]; tmp.u[1] = ho[2 * j4 + 1];
        hop[j4] = tmp.f;
    }

    // ---- z1 via folded Weff ((f,t) coalesced stores) ----
    float* z1p = g_z1 + (size_t)bid * 25600 + t;
    #pragma unroll 2
    for (int f = 0; f < 128; f++) {
        const float* wr = &s->weff[f * 64];
        u64 a0 = 0, a1 = 0, a2 = 0, a3 = 0, wa, wb;
        #pragma unroll
        for (int j4 = 0; j4 < 16; j4 += 2) {
            ld2x(&wr[j4 * 4], wa, wb);
            a0 = fma2(ho[2 * j4], wa, a0); a1 = fma2(ho[2 * j4 + 1], wb, a1);
            ld2x(&wr[j4 * 4 + 4], wa, wb);
            a2 = fma2(ho[2 * j4 + 2], wa, a2); a3 = fma2(ho[2 * j4 + 3], wb, a3);
        }
        z1p[f * 200] = (hsum2(a0) + hsum2(a1)) + (hsum2(a2) + hsum2(a3)) + s->c1b[f];
    }
}

// ---------------- stats stage 1: partial sums (grid = j*8 slices) ----------------
__global__ void __launch_bounds__(256) kP1()
{
    const int bid = blockIdx.x;          // 4096 blocks
    const int j = bid >> 3, sl = bid & 7;   // j = h*128+f
    const int h = j >> 7, f = j & 127;
    const int tid = threadIdx.x;
    float sm = 0.f, sq = 0.f;
    if (tid < 200) {
        const size_t base = ((size_t)h * 128 + f) * 200 + tid;
        for (int b0 = sl * 128; b0 < sl * 128 + 128; b0 += 8) {
            float v0 = g_z1[base + (size_t)(b0 + 0) * 102400];
            float v1 = g_z1[base + (size_t)(b0 + 1) * 102400];
            float v2 = g_z1[base + (size_t)(b0 + 2) * 102400];
            float v3 = g_z1[base + (size_t)(b0 + 3) * 102400];
            float v4 = g_z1[base + (size_t)(b0 + 4) * 102400];
            float v5 = g_z1[base + (size_t)(b0 + 5) * 102400];
            float v6 = g_z1[base + (size_t)(b0 + 6) * 102400];
            float v7 = g_z1[base + (size_t)(b0 + 7) * 102400];
            sm += ((v0 + v1) + (v2 + v3)) + ((v4 + v5) + (v6 + v7));
            sq += fmaf(v0, v0, fmaf(v1, v1, fmaf(v2, v2, v3 * v3)))
                + fmaf(v4, v4, fmaf(v5, v5, fmaf(v6, v6, v7 * v7)));
        }
    }
    __shared__ double rs[256], rq[256];
    rs[tid] = (double)sm; rq[tid] = (double)sq;
    __syncthreads();
    for (int o = 128; o > 0; o >>= 1) {
        if (tid < o) { rs[tid] += rs[tid + o]; rq[tid] += rq[tid + o]; }
        __syncthreads();
    }
    if (tid == 0) { g_p1[bid * 2] = rs[0]; g_p1[bid * 2 + 1] = rq[0]; }
}

__global__ void __launch_bounds__(512) kFin1()
{
    const int j = threadIdx.x;   // 512
    double sm = 0.0, sq = 0.0;
    for (int sl = 0; sl < 8; sl++) {
        sm += g_p1[(j * 8 + sl) * 2];
        sq += g_p1[(j * 8 + sl) * 2 + 1];
    }
    double N = 204800.0;
    double mean = sm / N;
    double var = sq / N - mean * mean;
    if (var < 0.0) var = 0.0;
    g_mean1[j] = (float)mean;
    g_istd1[j] = (float)(1.0 / sqrt(var + 1e-9));
}

__global__ void __launch_bounds__(256) kP2()
{
    const int bid = blockIdx.x;          // 2048 blocks
    const int j = bid >> 3, sl = bid & 7;   // j = h*64+g
    const int h = j >> 6, f = j & 63;
    const int tid = threadIdx.x;
    float sm = 0.f, sq = 0.f;
    if (tid < 200) {
        const size_t base = ((size_t)h * 64 + f) * 200 + tid;
        for (int b0 = sl * 128; b0 < sl * 128 + 128; b0 += 8) {
            float v0 = g_z2[base + (size_t)(b0 + 0) * 51200];
            float v1 = g_z2[base + (size_t)(b0 + 1) * 51200];
            float v2 = g_z2[base + (size_t)(b0 + 2) * 51200];
            float v3 = g_z2[base + (size_t)(b0 + 3) * 51200];
            float v4 = g_z2[base + (size_t)(b0 + 4) * 51200];
            float v5 = g_z2[base + (size_t)(b0 + 5) * 51200];
            float v6 = g_z2[base + (size_t)(b0 + 6) * 51200];
            float v7 = g_z2[base + (size_t)(b0 + 7) * 51200];
            sm += ((v0 + v1) + (v2 + v3)) + ((v4 + v5) + (v6 + v7));
            sq += fmaf(v0, v0, fmaf(v1, v1, fmaf(v2, v2, v3 * v3)))
                + fmaf(v4, v4, fmaf(v5, v5, fmaf(v6, v6, v7 * v7)));
        }
    }
    __shared__ double rs[256], rq[256];
    rs[tid] = (double)sm; rq[tid] = (double)sq;
    __syncthreads();
    for (int o = 128; o > 0; o >>= 1) {
        if (tid < o) { rs[tid] += rs[tid + o]; rq[tid] += rq[tid + o]; }
        __syncthreads();
    }
    if (tid == 0) { g_p2[bid * 2] = rs[0]; g_p2[bid * 2 + 1] = rq[0]; }
}

__global__ void __launch_bounds__(256) kFin2()
{
    const int j = threadIdx.x;   // 256
    double sm = 0.0, sq = 0.0;
    for (int sl = 0; sl < 8; sl++) {
        sm += g_p2[(j * 8 + sl) * 2];
        sq += g_p2[(j * 8 + sl) * 2 + 1];
    }
    double N = 204800.0;
    double mean = sm / N;
    double var = sq / N - mean * mean;
    if (var < 0.0) var = 0.0;
    g_mean2[j] = (float)mean;
    g_istd2[j] = (float)(1.0 / sqrt(var + 1e-9));
}

// ---------------- kernel C: dice1 + mw2 GEMM (f32x2) ----------------
__global__ void __launch_bounds__(256) kC(
    const float* __restrict__ mw2, const float* __restrict__ mb2,
    const float* __restrict__ alpha1)
{
    __shared__ float w2ts[8192];       // [f][g] transposed mw2
    __shared__ float mn[128], isd[128], al[128], mb[64];
    const int tid = threadIdx.x, bid = blockIdx.x, h = bid & 3;
    for (int i = tid; i < 8192; i += 256) {
        int f = i >> 6, g = i & 63;
        w2ts[i] = mw2[(size_t)h * 8192 + g * 128 + f];
    }
    if (tid < 128) {
        int j = h * 128 + tid;
        mn[tid] = g_mean1[j]; isd[tid] = g_istd1[j]; al[tid] = alpha1[j];
    }
    if (tid < 64) mb[tid] = mb2[h * 64 + tid];
    __syncthreads();
    if (tid >= 200) return;

    const float* zp = g_z1 + (size_t)bid * 25600 + tid;
    u64 acc[32];
    #pragma unroll
    for (int g = 0; g < 32; g++) acc[g] = 0ull;

    #pragma unroll 2
    for (int f = 0; f < 128; f++) {
        float zv = zp[f * 200];
        float xa = (zv - mn[f]) * isd[f];
        float p = __fdividef(1.f, 1.f + __expf(-xa));
        float xv = (p + al[f] * (1.f - p)) * zv;
        u64 xv2 = pack2(xv, xv);
        const float* wr = &w2ts[f * 64];
        u64 wa, wb;
        #pragma unroll
        for (int g4 = 0; g4 < 16; g4++) {
            ld2x(&wr[g4 * 4], wa, wb);
            acc[2 * g4]     = fma2(xv2, wa, acc[2 * g4]);
            acc[2 * g4 + 1] = fma2(xv2, wb, acc[2 * g4 + 1]);
        }
    }
    float* op = g_z2 + (size_t)bid * 12800 + tid;
    #pragma unroll
    for (int g4 = 0; g4 < 16; g4++) {
        float a, b, c, d;
        asm("mov.b64 {%0, %1}, %2;" : "=f"(a), "=f"(b) : "l"(acc[2 * g4]));
        asm("mov.b64 {%0, %1}, %2;" : "=f"(c), "=f"(d) : "l"(acc[2 * g4 + 1]));
        int g = g4 * 4;
        op[(g + 0) * 200] = a + mb[g + 0];
        op[(g + 1) * 200] = b + mb[g + 1];
        op[(g + 2) * 200] = c + mb[g + 2];
        op[(g + 3) * 200] = d + mb[g + 3];
    }
}

// ---------------- kernel E: dice2 + score + softmax + pooling ----------------
__global__ void __launch_bounds__(256) kE(
    const int* __restrict__ mask, const float* __restrict__ mw3,
    const float* __restrict__ mb3, const float* __restrict__ alpha2,
    float* __restrict__ out)
{
    __shared__ float w3s[64], m2s[64], i2s[64], a2s[64];
    __shared__ float red[256];
    __shared__ float wts[200];
    const int tid = threadIdx.x, bid = blockIdx.x;
    const int b = bid >> 2, h = bid & 3;
    if (tid < 64) {
        int j = h * 64 + tid;
        w3s[tid] = mw3[j]; m2s[tid] = g_mean2[j]; i2s[tid] = g_istd2[j]; a2s[tid] = alpha2[j];
    }
    __syncthreads();

    float sc = -3.0e38f;
    if (tid < 200) {
        const float* zp = g_z2 + (size_t)bid * 12800 + tid;
        float a = 0.f;
        #pragma unroll 4
        for (int g = 0; g < 64; g++) {
            float zv = zp[g * 200];
            float xa = (zv - m2s[g]) * i2s[g];
            float p = __fdividef(1.f, 1.f + __expf(-xa));
            float xv = (p + a2s[g] * (1.f - p)) * zv;
            a = fmaf(xv, w3s[g], a);
        }
        sc = a + mb3[h];
        if (mask[b * 200 + tid] == 0) sc = -1e9f;
    }
    red[tid] = sc;
    __syncthreads();
    for (int o = 128; o > 0; o >>= 1) {
        if (tid < o) red[tid] = fmaxf(red[tid], red[tid + o]);
        __syncthreads();
    }
    float mx = red[0];
    __syncthreads();
    float e = (tid < 200) ? __expf(sc - mx) : 0.f;
    red[tid] = e;
    __syncthreads();
    for (int o = 128; o > 0; o >>= 1) {
        if (tid < o) red[tid] += red[tid + o];
        __syncthreads();
    }
    float inv = 1.f / red[0];
    if (tid < 200) wts[tid] = e * inv;
    __syncthreads();

    const int c = tid >> 6, d = tid & 63;
    const float* hp = g_ho + (size_t)bid * 12800 + d;
    float acc = 0.f;
    #pragma unroll 2
    for (int t2 = c * 50; t2 < c * 50 + 50; t2++)
        acc = fmaf(wts[t2], hp[t2 * 64], acc);
    red[tid] = acc;
    __syncthreads();
    if (tid < 64)
        out[(size_t)bid * 64 + tid] = (red[tid] + red[tid + 64]) + (red[tid + 128] + red[tid + 192]);
}

// ---------------- launch ----------------
extern "C" void kernel_launch(void* const* d_in, const int* in_sizes, int n_in,
                              void* d_out, int out_size)
{
    const float* seq  = (const float*)d_in[0];
    const float* targ = (const float*)d_in[1];
    const int*   mask = (const int*)d_in[2];
    const float* Wqkv = (const float*)d_in[3];
    const float* Wo   = (const float*)d_in[4];
    const float* lng  = (const float*)d_in[5];
    const float* lnb  = (const float*)d_in[6];
    const float* fw1  = (const float*)d_in[7];
    const float* fb1  = (const float*)d_in[8];
    const float* fw2  = (const float*)d_in[9];
    const float* fb2  = (const float*)d_in[10];
    const float* mw1  = (const float*)d_in[11];
    const float* mb1  = (const float*)d_in[12];
    const float* a1   = (const float*)d_in[13];
    const float* mw2  = (const float*)d_in[14];
    const float* mb2  = (const float*)d_in[15];
    const float* a2   = (const float*)d_in[16];
    const float* mw3  = (const float*)d_in[17];
    const float* mb3  = (const float*)d_in[18];
    float* out = (float*)d_out;

    cudaFuncSetAttribute(kA, cudaFuncAttributeMaxDynamicSharedMemorySize, SMEM_A_BYTES);
    kA<<<4096, 256, SMEM_A_BYTES>>>(seq, targ, Wqkv, Wo, lng, lnb,
                                    fw1, fb1, fw2, fb2, mw1, mb1);
    kP1<<<4096, 256>>>();
    kFin1<<<1, 512>>>();
    kC<<<4096, 256>>>(mw2, mb2, a1);
    kP2<<<2048, 256>>>();
    kFin2<<<1, 256>>>();
    kE<<<4096, 256>>>(mask, mw3, mb3, a2, out);
}

// round 4
// speedup vs baseline: 1.2434x; 1.0643x over previous
#include <cuda_runtime.h>
#include <math.h>

typedef unsigned long long u64;

// ---------------- f32x2 packed helpers ----------------
__device__ __forceinline__ u64 fma2(u64 a, u64 b, u64 c) {
    u64 d; asm("fma.rn.f32x2 %0, %1, %2, %3;" : "=l"(d) : "l"(a), "l"(b), "l"(c)); return d;
}
__device__ __forceinline__ u64 pack2(float x, float y) {
    u64 r; asm("mov.b64 %0, {%1, %2};" : "=l"(r) : "f"(x), "f"(y)); return r;
}
__device__ __forceinline__ float hsum2(u64 v) {
    float a, b; asm("mov.b64 {%0, %1}, %2;" : "=f"(a), "=f"(b) : "l"(v)); return a + b;
}
__device__ __forceinline__ void unpack2(u64 v, float& a, float& b) {
    asm("mov.b64 {%0, %1}, %2;" : "=f"(a), "=f"(b) : "l"(v));
}
union F4U { float4 f; u64 u[2]; };
__device__ __forceinline__ void ld2x(const float* p, u64& a, u64& b) {
    F4U t; t.f = *(const float4*)p; a = t.u[0]; b = t.u[1];
}

// ---------------- scratch (no allocs allowed) ----------------
__device__ float g_ho[52428800];    // (b,h,d,t)  210 MB   [d-major, t contiguous]
__device__ float g_z1[104857600];   // (b,h,f,t)  419 MB
__device__ float g_z2[52428800];    // (b,h,g,t)  210 MB
__device__ double g_p1[4096 * 2];
__device__ double g_p2[2048 * 2];
__device__ float g_mean1[512], g_istd1[512];
__device__ float g_mean2[256], g_istd2[256];

// ---------------- kernel A smem layout (floats) ----------------
// kk 4000 | vv 4000 | wo 1024 | w1 4096 | w2t 4096 | uu 8192 (wq/wk/wv -> weff)
// c1b 128 | te 64 | lngs 64 | lnbs 64 | b1s 64 | b2s 64   => 25856 floats = 103424 B
constexpr int OFF_KK = 0;
constexpr int OFF_VV = 4000;
constexpr int OFF_WO = 8000;
constexpr int OFF_W1 = 9024;
constexpr int OFF_W2T = 13120;
constexpr int OFF_UU = 17216;
constexpr int OFF_C1 = 25408;
constexpr int OFF_TE = 25536;
constexpr int OFF_LNG = 25600;
constexpr int OFF_LNB = 25664;
constexpr int OFF_B1 = 25728;
constexpr int OFF_B2 = 25792;
constexpr int SMEM_A_FLOATS = 25856;
constexpr int SMEM_A_BYTES = SMEM_A_FLOATS * 4;

__global__ void __launch_bounds__(224, 2) kA(
    const float* __restrict__ seq, const float* __restrict__ targ,
    const float* __restrict__ Wqkv, const float* __restrict__ Wo,
    const float* __restrict__ lng, const float* __restrict__ lnb,
    const float* __restrict__ fw1, const float* __restrict__ fb1,
    const float* __restrict__ fw2, const float* __restrict__ fb2,
    const float* __restrict__ mw1, const float* __restrict__ mb1)
{
    extern __shared__ float sm[];
    float* kk  = sm + OFF_KK;
    float* vv  = sm + OFF_VV;
    float* wo  = sm + OFF_WO;
    float* w1  = sm + OFF_W1;
    float* w2t = sm + OFF_W2T;
    float* uu  = sm + OFF_UU;     // phase1: wq | wk | wv ; phase2: weff
    float* c1b = sm + OFF_C1;
    float* te  = sm + OFF_TE;
    float* lngs = sm + OFF_LNG;
    float* lnbs = sm + OFF_LNB;
    float* b1s = sm + OFF_B1;
    float* b2s = sm + OFF_B2;

    const int tid = threadIdx.x;
    const int bid = blockIdx.x;
    const int b = bid >> 2, h = bid & 3;

    // ---- cooperative loads ----
    for (int i = tid; i < 1024; i += 224) {
        int r = i >> 6, d = i & 63;
        uu[i]        = Wqkv[(h * 16 + r) * 64 + d];
        uu[1024 + i] = Wqkv[(64 + h * 16 + r) * 64 + d];
        uu[2048 + i] = Wqkv[(128 + h * 16 + r) * 64 + d];
        wo[i] = Wo[h * 1024 + i];
    }
    for (int i = tid; i < 4096; i += 224) {
        w1[i] = fw1[h * 4096 + i];
        int f = i >> 6, j = i & 63;
        w2t[i] = fw2[h * 4096 + j * 64 + f];
    }
    if (tid < 64) {
        te[tid]   = targ[b * 64 + tid];
        lngs[tid] = lng[h * 64 + tid];
        lnbs[tid] = lnb[h * 64 + tid];
        b1s[tid]  = fb1[h * 64 + tid];
        b2s[tid]  = fb2[h * 64 + tid];
    }
    __syncthreads();

    const bool act = tid < 200;
    const int t = act ? tid : 0;
    const int t20 = t * 20;

    // ---- own seq row into registers ----
    u64 xp[32];
    if (act) {
        const float* xr = seq + (size_t)b * 12800 + t * 64;
        #pragma unroll
        for (int j4 = 0; j4 < 16; j4++) ld2x(xr + j4 * 4, xp[2 * j4], xp[2 * j4 + 1]);
    }

    // ---- QKV (q in regs, k/v to smem) ----
    u64 qp[8];
    if (act) {
        float qv[16];
        #pragma unroll 4
        for (int i = 0; i < 16; i++) {
            u64 q0 = 0, q1 = 0, k0 = 0, k1 = 0, v0 = 0, v1 = 0, wa, wb;
            #pragma unroll
            for (int j4 = 0; j4 < 16; j4++) {
                ld2x(uu + i * 64 + j4 * 4, wa, wb);
                q0 = fma2(xp[2 * j4], wa, q0); q1 = fma2(xp[2 * j4 + 1], wb, q1);
                ld2x(uu + 1024 + i * 64 + j4 * 4, wa, wb);
                k0 = fma2(xp[2 * j4], wa, k0); k1 = fma2(xp[2 * j4 + 1], wb, k1);
                ld2x(uu + 2048 + i * 64 + j4 * 4, wa, wb);
                v0 = fma2(xp[2 * j4], wa, v0); v1 = fma2(xp[2 * j4 + 1], wb, v1);
            }
            qv[i] = hsum2(q0) + hsum2(q1);
            kk[t20 + i] = hsum2(k0) + hsum2(k1);
            vv[t20 + i] = hsum2(v0) + hsum2(v1);
        }
        #pragma unroll
        for (int ip = 0; ip < 8; ip++) qp[ip] = pack2(qv[2 * ip], qv[2 * ip + 1]);
    }
    __syncthreads();   // QKV done; uu region free

    // ---- fold mw1 -> weff (into uu) + c1 ----
    const float* m1h = mw1 + (size_t)h * 32768;
    for (int i = tid; i < 8192; i += 224) {
        int f = i >> 6, d = i & 63;
        const float* r = m1h + f * 256;
        uu[i] = r[64 + d] - r[128 + d] + te[d] * r[192 + d];
    }
    if (tid < 128) {
        const float* r = m1h + tid * 256;
        float a = mb1[h * 128 + tid];
        #pragma unroll 4
        for (int d = 0; d < 64; d++) a = fmaf(te[d], r[d] + r[128 + d], a);
        c1b[tid] = a;
    }
    __syncthreads();   // weff ready
    if (!act) return;

    // ---- attention (exp without max: scores bounded) ----
    u64 ctx[8];
    #pragma unroll
    for (int r = 0; r < 8; r++) ctx[r] = 0ull;
    float l = 0.f;
    #pragma unroll 2
    for (int t2 = 0; t2 < 200; t2++) {
        const float* kr = &kk[t2 * 20];
        u64 d0 = 0, d1 = 0, ka, kb;
        ld2x(kr,      ka, kb); d0 = fma2(qp[0], ka, d0); d1 = fma2(qp[1], kb, d1);
        ld2x(kr + 4,  ka, kb); d0 = fma2(qp[2], ka, d0); d1 = fma2(qp[3], kb, d1);
        ld2x(kr + 8,  ka, kb); d0 = fma2(qp[4], ka, d0); d1 = fma2(qp[5], kb, d1);
        ld2x(kr + 12, ka, kb); d0 = fma2(qp[6], ka, d0); d1 = fma2(qp[7], kb, d1);
        float p = __expf((hsum2(d0) + hsum2(d1)) * 0.25f);
        l += p;
        u64 pp = pack2(p, p);
        const float* vr = &vv[t2 * 20];
        u64 va, vb;
        ld2x(vr,      va, vb); ctx[0] = fma2(pp, va, ctx[0]); ctx[1] = fma2(pp, vb, ctx[1]);
        ld2x(vr + 4,  va, vb); ctx[2] = fma2(pp, va, ctx[2]); ctx[3] = fma2(pp, vb, ctx[3]);
        ld2x(vr + 8,  va, vb); ctx[4] = fma2(pp, va, ctx[4]); ctx[5] = fma2(pp, vb, ctx[5]);
        ld2x(vr + 12, va, vb); ctx[6] = fma2(pp, va, ctx[6]); ctx[7] = fma2(pp, vb, ctx[7]);
    }
    {
        float rl = 1.f / l;
        u64 rl2 = pack2(rl, rl);
        #pragma unroll
        for (int r = 0; r < 8; r++) ctx[r] = fma2(ctx[r], rl2, 0ull);
    }

    // ---- W_o + residual (into xp), LN stats ----
    u64 mu2 = 0ull, q22 = 0ull;
    const u64 one2 = pack2(1.f, 1.f);
    #pragma unroll 2
    for (int jp = 0; jp < 32; jp++) {
        const float* wr0 = &wo[(2 * jp) * 16];
        const float* wr1 = &wo[(2 * jp + 1) * 16];
        u64 a0 = 0, a1 = 0, b0 = 0, b1 = 0, wa, wb;
        ld2x(wr0,      wa, wb); a0 = fma2(ctx[0], wa, a0); a1 = fma2(ctx[1], wb, a1);
        ld2x(wr0 + 4,  wa, wb); a0 = fma2(ctx[2], wa, a0); a1 = fma2(ctx[3], wb, a1);
        ld2x(wr0 + 8,  wa, wb); a0 = fma2(ctx[4], wa, a0); a1 = fma2(ctx[5], wb, a1);
        ld2x(wr0 + 12, wa, wb); a0 = fma2(ctx[6], wa, a0); a1 = fma2(ctx[7], wb, a1);
        ld2x(wr1,      wa, wb); b0 = fma2(ctx[0], wa, b0); b1 = fma2(ctx[1], wb, b1);
        ld2x(wr1 + 4,  wa, wb); b0 = fma2(ctx[2], wa, b0); b1 = fma2(ctx[3], wb, b1);
        ld2x(wr1 + 8,  wa, wb); b0 = fma2(ctx[4], wa, b0); b1 = fma2(ctx[5], wb, b1);
        ld2x(wr1 + 12, wa, wb); b0 = fma2(ctx[6], wa, b0); b1 = fma2(ctx[7], wb, b1);
        float r0, r1;
        unpack2(xp[jp], r0, r1);
        float s0 = hsum2(a0) + hsum2(a1) + r0;
        float s1 = hsum2(b0) + hsum2(b1) + r1;
        u64 sp = pack2(s0, s1);
        xp[jp] = sp;
        mu2 = fma2(sp, one2, mu2);
        q22 = fma2(sp, sp, q22);
    }
    float mu = hsum2(mu2) * (1.f / 64.f);
    float var = hsum2(q22) * (1.f / 64.f) - mu * mu;
    float rstd = rsqrtf(var + 1e-5f);

    // ---- LN in place: xp := srg ----
    {
        u64 rstd2 = pack2(rstd, rstd);
        float nm = -mu * rstd;
        u64 nmr = pack2(nm, nm);
        #pragma unroll
        for (int j4 = 0; j4 < 16; j4++) {
            u64 ga, gb, ba, bb;
            ld2x(&lngs[j4 * 4], ga, gb);
            ld2x(&lnbs[j4 * 4], ba, bb);
            xp[2 * j4]     = fma2(fma2(xp[2 * j4],     rstd2, nmr), ga, ba);
            xp[2 * j4 + 1] = fma2(fma2(xp[2 * j4 + 1], rstd2, nmr), gb, bb);
        }
    }

    // ---- FFN pass 1: all h1 (packed pairs) ----
    u64 h1p[32];
    #pragma unroll 2
    for (int fp = 0; fp < 32; fp++) {
        const float* w0 = &w1[(2 * fp) * 64];
        const float* wB = &w1[(2 * fp + 1) * 64];
        u64 a0 = 0, a1 = 0, b0 = 0, b1 = 0, wa, wb;
        #pragma unroll
        for (int j4 = 0; j4 < 16; j4++) {
            ld2x(&w0[j4 * 4], wa, wb);
            a0 = fma2(xp[2 * j4], wa, a0); a1 = fma2(xp[2 * j4 + 1], wb, a1);
            ld2x(&wB[j4 * 4], wa, wb);
            b0 = fma2(xp[2 * j4], wa, b0); b1 = fma2(xp[2 * j4 + 1], wb, b1);
        }
        float hA = fmaxf(hsum2(a0) + hsum2(a1) + b1s[2 * fp], 0.f);
        float hB = fmaxf(hsum2(b0) + hsum2(b1) + b1s[2 * fp + 1], 0.f);
        h1p[fp] = pack2(hA, hB);
    }

    // ---- FFN pass 2: xp := ho = srg + b2 + W2^T h1 ----
    #pragma unroll
    for (int j4 = 0; j4 < 16; j4++) {
        u64 ca, cb;
        ld2x(&b2s[j4 * 4], ca, cb);
        xp[2 * j4]     = fma2(xp[2 * j4],     one2, ca);
        xp[2 * j4 + 1] = fma2(xp[2 * j4 + 1], one2, cb);
    }
    #pragma unroll 2
    for (int fp = 0; fp < 32; fp++) {
        float hA, hB;
        unpack2(h1p[fp], hA, hB);
        u64 hA2 = pack2(hA, hA), hB2 = pack2(hB, hB);
        const float* r0 = &w2t[(2 * fp) * 64];
        const float* r1 = &w2t[(2 * fp + 1) * 64];
        u64 wa, wb;
        #pragma unroll
        for (int j4 = 0; j4 < 16; j4++) {
            ld2x(&r0[j4 * 4], wa, wb);
            xp[2 * j4]     = fma2(hA2, wa, xp[2 * j4]);
            xp[2 * j4 + 1] = fma2(hA2, wb, xp[2 * j4 + 1]);
        }
        #pragma unroll
        for (int j4 = 0; j4 < 16; j4++) {
            ld2x(&r1[j4 * 4], wa, wb);
            xp[2 * j4]     = fma2(hB2, wa, xp[2 * j4]);
            xp[2 * j4 + 1] = fma2(hB2, wb, xp[2 * j4 + 1]);
        }
    }

    // ---- store head_out in (d,t) layout: fully coalesced scalars ----
    {
        float* hop = g_ho + (size_t)bid * 12800 + t;
        #pragma unroll
        for (int jp = 0; jp < 32; jp++) {
            float a, c;
            unpack2(xp[jp], a, c);
            hop[(2 * jp) * 200] = a;
            hop[(2 * jp + 1) * 200] = c;
        }
    }

    // ---- z1 via folded weff (coalesced (f,t) stores) ----
    float* z1p = g_z1 + (size_t)bid * 25600 + t;
    #pragma unroll 2
    for (int f = 0; f < 128; f++) {
        const float* wr = &uu[f * 64];
        u64 a0 = 0, a1 = 0, a2 = 0, a3 = 0, wa, wb;
        #pragma unroll
        for (int j4 = 0; j4 < 16; j4 += 2) {
            ld2x(&wr[j4 * 4], wa, wb);
            a0 = fma2(xp[2 * j4], wa, a0); a1 = fma2(xp[2 * j4 + 1], wb, a1);
            ld2x(&wr[j4 * 4 + 4], wa, wb);
            a2 = fma2(xp[2 * j4 + 2], wa, a2); a3 = fma2(xp[2 * j4 + 3], wb, a3);
        }
        z1p[f * 200] = (hsum2(a0) + hsum2(a1)) + (hsum2(a2) + hsum2(a3)) + c1b[f];
    }
}

// ---------------- stats stage 1 ----------------
__global__ void __launch_bounds__(256) kP1()
{
    const int bid = blockIdx.x;          // 4096 blocks
    const int j = bid >> 3, sl = bid & 7;
    const int h = j >> 7, f = j & 127;
    const int tid = threadIdx.x;
    float sm = 0.f, sq = 0.f;
    if (tid < 200) {
        const size_t base = ((size_t)h * 128 + f) * 200 + tid;
        for (int b0 = sl * 128; b0 < sl * 128 + 128; b0 += 8) {
            float v0 = g_z1[base + (size_t)(b0 + 0) * 102400];
            float v1 = g_z1[base + (size_t)(b0 + 1) * 102400];
            float v2 = g_z1[base + (size_t)(b0 + 2) * 102400];
            float v3 = g_z1[base + (size_t)(b0 + 3) * 102400];
            float v4 = g_z1[base + (size_t)(b0 + 4) * 102400];
            float v5 = g_z1[base + (size_t)(b0 + 5) * 102400];
            float v6 = g_z1[base + (size_t)(b0 + 6) * 102400];
            float v7 = g_z1[base + (size_t)(b0 + 7) * 102400];
            sm += ((v0 + v1) + (v2 + v3)) + ((v4 + v5) + (v6 + v7));
            sq += fmaf(v0, v0, fmaf(v1, v1, fmaf(v2, v2, v3 * v3)))
                + fmaf(v4, v4, fmaf(v5, v5, fmaf(v6, v6, v7 * v7)));
        }
    }
    __shared__ double rs[256], rq[256];
    rs[tid] = (double)sm; rq[tid] = (double)sq;
    __syncthreads();
    for (int o = 128; o > 0; o >>= 1) {
        if (tid < o) { rs[tid] += rs[tid + o]; rq[tid] += rq[tid + o]; }
        __syncthreads();
    }
    if (tid == 0) { g_p1[bid * 2] = rs[0]; g_p1[bid * 2 + 1] = rq[0]; }
}

__global__ void __launch_bounds__(512) kFin1()
{
    const int j = threadIdx.x;   // 512
    double sm = 0.0, sq = 0.0;
    for (int sl = 0; sl < 8; sl++) {
        sm += g_p1[(j * 8 + sl) * 2];
        sq += g_p1[(j * 8 + sl) * 2 + 1];
    }
    double N = 204800.0;
    double mean = sm / N;
    double var = sq / N - mean * mean;
    if (var < 0.0) var = 0.0;
    g_mean1[j] = (float)mean;
    g_istd1[j] = (float)(1.0 / sqrt(var + 1e-9));
}

__global__ void __launch_bounds__(256) kP2()
{
    const int bid = blockIdx.x;          // 2048 blocks
    const int j = bid >> 3, sl = bid & 7;
    const int h = j >> 6, f = j & 63;
    const int tid = threadIdx.x;
    float sm = 0.f, sq = 0.f;
    if (tid < 200) {
        const size_t base = ((size_t)h * 64 + f) * 200 + tid;
        for (int b0 = sl * 128; b0 < sl * 128 + 128; b0 += 8) {
            float v0 = g_z2[base + (size_t)(b0 + 0) * 51200];
            float v1 = g_z2[base + (size_t)(b0 + 1) * 51200];
            float v2 = g_z2[base + (size_t)(b0 + 2) * 51200];
            float v3 = g_z2[base + (size_t)(b0 + 3) * 51200];
            float v4 = g_z2[base + (size_t)(b0 + 4) * 51200];
            float v5 = g_z2[base + (size_t)(b0 + 5) * 51200];
            float v6 = g_z2[base + (size_t)(b0 + 6) * 51200];
            float v7 = g_z2[base + (size_t)(b0 + 7) * 51200];
            sm += ((v0 + v1) + (v2 + v3)) + ((v4 + v5) + (v6 + v7));
            sq += fmaf(v0, v0, fmaf(v1, v1, fmaf(v2, v2, v3 * v3)))
                + fmaf(v4, v4, fmaf(v5, v5, fmaf(v6, v6, v7 * v7)));
        }
    }
    __shared__ double rs[256], rq[256];
    rs[tid] = (double)sm; rq[tid] = (double)sq;
    __syncthreads();
    for (int o = 128; o > 0; o >>= 1) {
        if (tid < o) { rs[tid] += rs[tid + o]; rq[tid] += rq[tid + o]; }
        __syncthreads();
    }
    if (tid == 0) { g_p2[bid * 2] = rs[0]; g_p2[bid * 2 + 1] = rq[0]; }
}

__global__ void __launch_bounds__(256) kFin2()
{
    const int j = threadIdx.x;   // 256
    double sm = 0.0, sq = 0.0;
    for (int sl = 0; sl < 8; sl++) {
        sm += g_p2[(j * 8 + sl) * 2];
        sq += g_p2[(j * 8 + sl) * 2 + 1];
    }
    double N = 204800.0;
    double mean = sm / N;
    double var = sq / N - mean * mean;
    if (var < 0.0) var = 0.0;
    g_mean2[j] = (float)mean;
    g_istd2[j] = (float)(1.0 / sqrt(var + 1e-9));
}

// ---------------- kernel C: dice1 + mw2 GEMM, g-split halves ----------------
__global__ void __launch_bounds__(256, 3) kC(
    const float* __restrict__ mw2, const float* __restrict__ mb2,
    const float* __restrict__ alpha1)
{
    __shared__ float w2ts[4096];       // [f][32] transposed half of mw2
    __shared__ float mn[128], isd[128], al[128], mbs[32];
    const int tid = threadIdx.x;
    const int bh = blockIdx.x >> 1, half = blockIdx.x & 1;
    const int h = bh & 3;
    for (int i = tid; i < 4096; i += 256) {
        int f = i >> 5, g = i & 31;
        w2ts[i] = mw2[(size_t)h * 8192 + (half * 32 + g) * 128 + f];
    }
    if (tid < 128) {
        int j = h * 128 + tid;
        mn[tid] = g_mean1[j]; isd[tid] = g_istd1[j]; al[tid] = alpha1[j];
    }
    if (tid < 32) mbs[tid] = mb2[h * 64 + half * 32 + tid];
    __syncthreads();
    if (tid >= 200) return;

    const float* zp = g_z1 + (size_t)bh * 25600 + tid;
    u64 acc[16];
    #pragma unroll
    for (int g = 0; g < 16; g++) acc[g] = 0ull;

    #pragma unroll 2
    for (int f = 0; f < 128; f++) {
        float zv = zp[f * 200];
        float xa = (zv - mn[f]) * isd[f];
        float p = __fdividef(1.f, 1.f + __expf(-xa));
        float xv = (p + al[f] * (1.f - p)) * zv;
        u64 xv2 = pack2(xv, xv);
        const float* wr = &w2ts[f * 32];
        u64 wa, wb;
        #pragma unroll
        for (int g4 = 0; g4 < 8; g4++) {
            ld2x(&wr[g4 * 4], wa, wb);
            acc[2 * g4]     = fma2(xv2, wa, acc[2 * g4]);
            acc[2 * g4 + 1] = fma2(xv2, wb, acc[2 * g4 + 1]);
        }
    }
    float* op = g_z2 + (size_t)bh * 12800 + (size_t)half * 32 * 200 + tid;
    #pragma unroll
    for (int g4 = 0; g4 < 8; g4++) {
        float a, b, c, d;
        unpack2(acc[2 * g4], a, b);
        unpack2(acc[2 * g4 + 1], c, d);
        int g = g4 * 4;
        op[(g + 0) * 200] = a + mbs[g + 0];
        op[(g + 1) * 200] = b + mbs[g + 1];
        op[(g + 2) * 200] = c + mbs[g + 2];
        op[(g + 3) * 200] = d + mbs[g + 3];
    }
}

// ---------------- kernel E: dice2 + score + softmax + pooling ----------------
__global__ void __launch_bounds__(256) kE(
    const int* __restrict__ mask, const float* __restrict__ mw3,
    const float* __restrict__ mb3, const float* __restrict__ alpha2,
    float* __restrict__ out)
{
    __shared__ float w3s[64], m2s[64], i2s[64], a2s[64];
    __shared__ float red[256];
    __shared__ float wts[200];
    const int tid = threadIdx.x, bid = blockIdx.x;
    const int b = bid >> 2, h = bid & 3;
    if (tid < 64) {
        int j = h * 64 + tid;
        w3s[tid] = mw3[j]; m2s[tid] = g_mean2[j]; i2s[tid] = g_istd2[j]; a2s[tid] = alpha2[j];
    }
    __syncthreads();

    float sc = -3.0e38f;
    if (tid < 200) {
        const float* zp = g_z2 + (size_t)bid * 12800 + tid;
        float a = 0.f;
        #pragma unroll 4
        for (int g = 0; g < 64; g++) {
            float zv = zp[g * 200];
            float xa = (zv - m2s[g]) * i2s[g];
            float p = __fdividef(1.f, 1.f + __expf(-xa));
            float xv = (p + a2s[g] * (1.f - p)) * zv;
            a = fmaf(xv, w3s[g], a);
        }
        sc = a + mb3[h];
        if (mask[b * 200 + tid] == 0) sc = -1e9f;
    }
    red[tid] = sc;
    __syncthreads();
    for (int o = 128; o > 0; o >>= 1) {
        if (tid < o) red[tid] = fmaxf(red[tid], red[tid + o]);
        __syncthreads();
    }
    float mx = red[0];
    __syncthreads();
    float e = (tid < 200) ? __expf(sc - mx) : 0.f;
    red[tid] = e;
    __syncthreads();
    for (int o = 128; o > 0; o >>= 1) {
        if (tid < o) red[tid] += red[tid + o];
        __syncthreads();
    }
    float inv = 1.f / red[0];
    if (tid < 200) wts[tid] = e * inv;
    __syncthreads();

    // pooling over (d,t) layout: thread = (chunk c, dim d)
    const int c = tid >> 6, d = tid & 63;
    const float* hp = g_ho + (size_t)bid * 12800 + d * 200 + c * 50;
    float acc = 0.f;
    #pragma unroll 2
    for (int i = 0; i < 50; i++)
        acc = fmaf(wts[c * 50 + i], hp[i], acc);
    red[tid] = acc;
    __syncthreads();
    if (tid < 64)
        out[(size_t)bid * 64 + tid] = (red[tid] + red[tid + 64]) + (red[tid + 128] + red[tid + 192]);
}

// ---------------- launch ----------------
extern "C" void kernel_launch(void* const* d_in, const int* in_sizes, int n_in,
                              void* d_out, int out_size)
{
    const float* seq  = (const float*)d_in[0];
    const float* targ = (const float*)d_in[1];
    const int*   mask = (const int*)d_in[2];
    const float* Wqkv = (const float*)d_in[3];
    const float* Wo   = (const float*)d_in[4];
    const float* lng  = (const float*)d_in[5];
    const float* lnb  = (const float*)d_in[6];
    const float* fw1  = (const float*)d_in[7];
    const float* fb1  = (const float*)d_in[8];
    const float* fw2  = (const float*)d_in[9];
    const float* fb2  = (const float*)d_in[10];
    const float* mw1  = (const float*)d_in[11];
    const float* mb1  = (const float*)d_in[12];
    const float* a1   = (const float*)d_in[13];
    const float* mw2  = (const float*)d_in[14];
    const float* mb2  = (const float*)d_in[15];
    const float* a2   = (const float*)d_in[16];
    const float* mw3  = (const float*)d_in[17];
    const float* mb3  = (const float*)d_in[18];
    float* out = (float*)d_out;

    cudaFuncSetAttribute(kA, cudaFuncAttributeMaxDynamicSharedMemorySize, SMEM_A_BYTES);
    kA<<<4096, 224, SMEM_A_BYTES>>>(seq, targ, Wqkv, Wo, lng, lnb,
                                    fw1, fb1, fw2, fb2, mw1, mb1);
    kP1<<<4096, 256>>>();
    kFin1<<<1, 512>>>();
    kC<<<8192, 256>>>(mw2, mb2, a1);
    kP2<<<2048, 256>>>();
    kFin2<<<1, 256>>>();
    kE<<<4096, 256>>>(mask, mw3, mb3, a2, out);
}

// round 5
// speedup vs baseline: 1.2647x; 1.0172x over previous
#include <cuda_runtime.h>
#include <math.h>

typedef unsigned long long u64;

// ---------------- f32x2 packed helpers ----------------
__device__ __forceinline__ u64 fma2(u64 a, u64 b, u64 c) {
    u64 d; asm("fma.rn.f32x2 %0, %1, %2, %3;" : "=l"(d) : "l"(a), "l"(b), "l"(c)); return d;
}
__device__ __forceinline__ u64 pack2(float x, float y) {
    u64 r; asm("mov.b64 %0, {%1, %2};" : "=l"(r) : "f"(x), "f"(y)); return r;
}
__device__ __forceinline__ float hsum2(u64 v) {
    float a, b; asm("mov.b64 {%0, %1}, %2;" : "=f"(a), "=f"(b) : "l"(v)); return a + b;
}
__device__ __forceinline__ void unpack2(u64 v, float& a, float& b) {
    asm("mov.b64 {%0, %1}, %2;" : "=f"(a), "=f"(b) : "l"(v));
}
union F4U { float4 f; u64 u[2]; };
__device__ __forceinline__ void ld2x(const float* p, u64& a, u64& b) {
    F4U t; t.f = *(const float4*)p; a = t.u[0]; b = t.u[1];
}

// ---------------- scratch (no allocs allowed) ----------------
__device__ float g_ho[52428800];    // (b,h,d,t)  210 MB
__device__ float g_z1[104857600];   // (b,h,f,t)  419 MB
__device__ float g_z2[52428800];    // (b,h,g,t)  210 MB
__device__ double g_p1[4096 * 2];
__device__ double g_p2[2048 * 2];
__device__ float g_mean1[512], g_istd1[512];
__device__ float g_mean2[256], g_istd2[256];

// ---------------- kernel A smem layout (floats) ----------------
constexpr int OFF_KK = 0;
constexpr int OFF_VV = 4000;
constexpr int OFF_WO = 8000;
constexpr int OFF_W1 = 9024;
constexpr int OFF_W2T = 13120;
constexpr int OFF_UU = 17216;
constexpr int OFF_C1 = 25408;
constexpr int OFF_TE = 25536;
constexpr int OFF_LNG = 25600;
constexpr int OFF_LNB = 25664;
constexpr int OFF_B1 = 25728;
constexpr int OFF_B2 = 25792;
constexpr int SMEM_A_FLOATS = 25856;
constexpr int SMEM_A_BYTES = SMEM_A_FLOATS * 4;

__global__ void __launch_bounds__(224, 2) kA(
    const float* __restrict__ seq, const float* __restrict__ targ,
    const float* __restrict__ Wqkv, const float* __restrict__ Wo,
    const float* __restrict__ lng, const float* __restrict__ lnb,
    const float* __restrict__ fw1, const float* __restrict__ fb1,
    const float* __restrict__ fw2, const float* __restrict__ fb2,
    const float* __restrict__ mw1, const float* __restrict__ mb1)
{
    extern __shared__ float sm[];
    float* kk  = sm + OFF_KK;
    float* vv  = sm + OFF_VV;
    float* wo  = sm + OFF_WO;
    float* w1  = sm + OFF_W1;
    float* w2t = sm + OFF_W2T;
    float* uu  = sm + OFF_UU;     // phase1: wq | wk | wv ; phase2: weff
    float* c1b = sm + OFF_C1;
    float* te  = sm + OFF_TE;
    float* lngs = sm + OFF_LNG;
    float* lnbs = sm + OFF_LNB;
    float* b1s = sm + OFF_B1;
    float* b2s = sm + OFF_B2;

    const int tid = threadIdx.x;
    const int bid = blockIdx.x;
    const int b = bid >> 2, h = bid & 3;

    // ---- cooperative loads ----
    for (int i = tid; i < 1024; i += 224) {
        int r = i >> 6, d = i & 63;
        uu[i]        = Wqkv[(h * 16 + r) * 64 + d];
        uu[1024 + i] = Wqkv[(64 + h * 16 + r) * 64 + d];
        uu[2048 + i] = Wqkv[(128 + h * 16 + r) * 64 + d];
        wo[i] = Wo[h * 1024 + i];
    }
    for (int i = tid; i < 4096; i += 224) {
        w1[i] = fw1[h * 4096 + i];
        int f = i >> 6, j = i & 63;
        w2t[i] = fw2[h * 4096 + j * 64 + f];
    }
    if (tid < 64) {
        te[tid]   = targ[b * 64 + tid];
        lngs[tid] = lng[h * 64 + tid];
        lnbs[tid] = lnb[h * 64 + tid];
        b1s[tid]  = fb1[h * 64 + tid];
        b2s[tid]  = fb2[h * 64 + tid];
    }
    __syncthreads();

    const bool act = tid < 200;
    const int t = act ? tid : 0;
    const int t20 = t * 20;

    // ---- own seq row into registers ----
    u64 xp[32];
    if (act) {
        const float* xr = seq + (size_t)b * 12800 + t * 64;
        #pragma unroll
        for (int j4 = 0; j4 < 16; j4++) ld2x(xr + j4 * 4, xp[2 * j4], xp[2 * j4 + 1]);
    }

    // ---- QKV (q in regs, k/v to smem) ----
    u64 qp[8];
    if (act) {
        float qv[16];
        #pragma unroll 4
        for (int i = 0; i < 16; i++) {
            u64 q0 = 0, q1 = 0, k0 = 0, k1 = 0, v0 = 0, v1 = 0, wa, wb;
            #pragma unroll
            for (int j4 = 0; j4 < 16; j4++) {
                ld2x(uu + i * 64 + j4 * 4, wa, wb);
                q0 = fma2(xp[2 * j4], wa, q0); q1 = fma2(xp[2 * j4 + 1], wb, q1);
                ld2x(uu + 1024 + i * 64 + j4 * 4, wa, wb);
                k0 = fma2(xp[2 * j4], wa, k0); k1 = fma2(xp[2 * j4 + 1], wb, k1);
                ld2x(uu + 2048 + i * 64 + j4 * 4, wa, wb);
                v0 = fma2(xp[2 * j4], wa, v0); v1 = fma2(xp[2 * j4 + 1], wb, v1);
            }
            qv[i] = hsum2(q0) + hsum2(q1);
            kk[t20 + i] = hsum2(k0) + hsum2(k1);
            vv[t20 + i] = hsum2(v0) + hsum2(v1);
        }
        #pragma unroll
        for (int ip = 0; ip < 8; ip++) qp[ip] = pack2(qv[2 * ip], qv[2 * ip + 1]);
    }
    __syncthreads();   // QKV done; uu region free

    // ---- fold mw1 -> weff (into uu) + c1 ----
    const float* m1h = mw1 + (size_t)h * 32768;
    for (int i = tid; i < 8192; i += 224) {
        int f = i >> 6, d = i & 63;
        const float* r = m1h + f * 256;
        uu[i] = r[64 + d] - r[128 + d] + te[d] * r[192 + d];
    }
    if (tid < 128) {
        const float* r = m1h + tid * 256;
        float a = mb1[h * 128 + tid];
        #pragma unroll 4
        for (int d = 0; d < 64; d++) a = fmaf(te[d], r[d] + r[128 + d], a);
        c1b[tid] = a;
    }
    __syncthreads();   // weff ready
    if (!act) return;

    // ---- attention (exp without max: scores bounded) ----
    u64 ctx[8];
    #pragma unroll
    for (int r = 0; r < 8; r++) ctx[r] = 0ull;
    float l = 0.f;
    #pragma unroll 2
    for (int t2 = 0; t2 < 200; t2++) {
        const float* kr = &kk[t2 * 20];
        u64 d0 = 0, d1 = 0, ka, kb;
        ld2x(kr,      ka, kb); d0 = fma2(qp[0], ka, d0); d1 = fma2(qp[1], kb, d1);
        ld2x(kr + 4,  ka, kb); d0 = fma2(qp[2], ka, d0); d1 = fma2(qp[3], kb, d1);
        ld2x(kr + 8,  ka, kb); d0 = fma2(qp[4], ka, d0); d1 = fma2(qp[5], kb, d1);
        ld2x(kr + 12, ka, kb); d0 = fma2(qp[6], ka, d0); d1 = fma2(qp[7], kb, d1);
        float p = __expf((hsum2(d0) + hsum2(d1)) * 0.25f);
        l += p;
        u64 pp = pack2(p, p);
        const float* vr = &vv[t2 * 20];
        u64 va, vb;
        ld2x(vr,      va, vb); ctx[0] = fma2(pp, va, ctx[0]); ctx[1] = fma2(pp, vb, ctx[1]);
        ld2x(vr + 4,  va, vb); ctx[2] = fma2(pp, va, ctx[2]); ctx[3] = fma2(pp, vb, ctx[3]);
        ld2x(vr + 8,  va, vb); ctx[4] = fma2(pp, va, ctx[4]); ctx[5] = fma2(pp, vb, ctx[5]);
        ld2x(vr + 12, va, vb); ctx[6] = fma2(pp, va, ctx[6]); ctx[7] = fma2(pp, vb, ctx[7]);
    }
    {
        float rl = 1.f / l;
        u64 rl2 = pack2(rl, rl);
        #pragma unroll
        for (int r = 0; r < 8; r++) ctx[r] = fma2(ctx[r], rl2, 0ull);
    }

    // ---- W_o + residual (into xp), LN stats ----
    u64 mu2 = 0ull, q22 = 0ull;
    const u64 one2 = pack2(1.f, 1.f);
    #pragma unroll 2
    for (int jp = 0; jp < 32; jp++) {
        const float* wr0 = &wo[(2 * jp) * 16];
        const float* wr1 = &wo[(2 * jp + 1) * 16];
        u64 a0 = 0, a1 = 0, b0 = 0, b1 = 0, wa, wb;
        ld2x(wr0,      wa, wb); a0 = fma2(ctx[0], wa, a0); a1 = fma2(ctx[1], wb, a1);
        ld2x(wr0 + 4,  wa, wb); a0 = fma2(ctx[2], wa, a0); a1 = fma2(ctx[3], wb, a1);
        ld2x(wr0 + 8,  wa, wb); a0 = fma2(ctx[4], wa, a0); a1 = fma2(ctx[5], wb, a1);
        ld2x(wr0 + 12, wa, wb); a0 = fma2(ctx[6], wa, a0); a1 = fma2(ctx[7], wb, a1);
        ld2x(wr1,      wa, wb); b0 = fma2(ctx[0], wa, b0); b1 = fma2(ctx[1], wb, b1);
        ld2x(wr1 + 4,  wa, wb); b0 = fma2(ctx[2], wa, b0); b1 = fma2(ctx[3], wb, b1);
        ld2x(wr1 + 8,  wa, wb); b0 = fma2(ctx[4], wa, b0); b1 = fma2(ctx[5], wb, b1);
        ld2x(wr1 + 12, wa, wb); b0 = fma2(ctx[6], wa, b0); b1 = fma2(ctx[7], wb, b1);
        float r0, r1;
        unpack2(xp[jp], r0, r1);
        float s0 = hsum2(a0) + hsum2(a1) + r0;
        float s1 = hsum2(b0) + hsum2(b1) + r1;
        u64 sp = pack2(s0, s1);
        xp[jp] = sp;
        mu2 = fma2(sp, one2, mu2);
        q22 = fma2(sp, sp, q22);
    }
    float mu = hsum2(mu2) * (1.f / 64.f);
    float var = hsum2(q22) * (1.f / 64.f) - mu * mu;
    float rstd = rsqrtf(var + 1e-5f);

    // ---- LN in place: xp := srg ----
    {
        u64 rstd2 = pack2(rstd, rstd);
        float nm = -mu * rstd;
        u64 nmr = pack2(nm, nm);
        #pragma unroll
        for (int j4 = 0; j4 < 16; j4++) {
            u64 ga, gb, ba, bb;
            ld2x(&lngs[j4 * 4], ga, gb);
            ld2x(&lnbs[j4 * 4], ba, bb);
            xp[2 * j4]     = fma2(fma2(xp[2 * j4],     rstd2, nmr), ga, ba);
            xp[2 * j4 + 1] = fma2(fma2(xp[2 * j4 + 1], rstd2, nmr), gb, bb);
        }
    }

    // ---- FFN pass 1: all h1 (packed pairs) ----
    u64 h1p[32];
    #pragma unroll 2
    for (int fp = 0; fp < 32; fp++) {
        const float* w0 = &w1[(2 * fp) * 64];
        const float* wB = &w1[(2 * fp + 1) * 64];
        u64 a0 = 0, a1 = 0, b0 = 0, b1 = 0, wa, wb;
        #pragma unroll
        for (int j4 = 0; j4 < 16; j4++) {
            ld2x(&w0[j4 * 4], wa, wb);
            a0 = fma2(xp[2 * j4], wa, a0); a1 = fma2(xp[2 * j4 + 1], wb, a1);
            ld2x(&wB[j4 * 4], wa, wb);
            b0 = fma2(xp[2 * j4], wa, b0); b1 = fma2(xp[2 * j4 + 1], wb, b1);
        }
        float hA = fmaxf(hsum2(a0) + hsum2(a1) + b1s[2 * fp], 0.f);
        float hB = fmaxf(hsum2(b0) + hsum2(b1) + b1s[2 * fp + 1], 0.f);
        h1p[fp] = pack2(hA, hB);
    }

    // ---- FFN pass 2: xp := ho = srg + b2 + W2^T h1 ----
    #pragma unroll
    for (int j4 = 0; j4 < 16; j4++) {
        u64 ca, cb;
        ld2x(&b2s[j4 * 4], ca, cb);
        xp[2 * j4]     = fma2(xp[2 * j4],     one2, ca);
        xp[2 * j4 + 1] = fma2(xp[2 * j4 + 1], one2, cb);
    }
    #pragma unroll 2
    for (int fp = 0; fp < 32; fp++) {
        float hA, hB;
        unpack2(h1p[fp], hA, hB);
        u64 hA2 = pack2(hA, hA), hB2 = pack2(hB, hB);
        const float* r0 = &w2t[(2 * fp) * 64];
        const float* r1 = &w2t[(2 * fp + 1) * 64];
        u64 wa, wb;
        #pragma unroll
        for (int j4 = 0; j4 < 16; j4++) {
            ld2x(&r0[j4 * 4], wa, wb);
            xp[2 * j4]     = fma2(hA2, wa, xp[2 * j4]);
            xp[2 * j4 + 1] = fma2(hA2, wb, xp[2 * j4 + 1]);
        }
        #pragma unroll
        for (int j4 = 0; j4 < 16; j4++) {
            ld2x(&r1[j4 * 4], wa, wb);
            xp[2 * j4]     = fma2(hB2, wa, xp[2 * j4]);
            xp[2 * j4 + 1] = fma2(hB2, wb, xp[2 * j4 + 1]);
        }
    }

    // ---- store head_out in (d,t) layout ----
    {
        float* hop = g_ho + (size_t)bid * 12800 + t;
        #pragma unroll
        for (int jp = 0; jp < 32; jp++) {
            float a, c;
            unpack2(xp[jp], a, c);
            hop[(2 * jp) * 200] = a;
            hop[(2 * jp + 1) * 200] = c;
        }
    }

    // ---- z1 via folded weff (coalesced (f,t) stores) ----
    float* z1p = g_z1 + (size_t)bid * 25600 + t;
    #pragma unroll 2
    for (int f = 0; f < 128; f++) {
        const float* wr = &uu[f * 64];
        u64 a0 = 0, a1 = 0, a2 = 0, a3 = 0, wa, wb;
        #pragma unroll
        for (int j4 = 0; j4 < 16; j4 += 2) {
            ld2x(&wr[j4 * 4], wa, wb);
            a0 = fma2(xp[2 * j4], wa, a0); a1 = fma2(xp[2 * j4 + 1], wb, a1);
            ld2x(&wr[j4 * 4 + 4], wa, wb);
            a2 = fma2(xp[2 * j4 + 2], wa, a2); a3 = fma2(xp[2 * j4 + 3], wb, a3);
        }
        z1p[f * 200] = (hsum2(a0) + hsum2(a1)) + (hsum2(a2) + hsum2(a3)) + c1b[f];
    }
}

// ---------------- stats stage 1 ----------------
__global__ void __launch_bounds__(256) kP1()
{
    const int bid = blockIdx.x;          // 4096 blocks
    const int j = bid >> 3, sl = bid & 7;
    const int h = j >> 7, f = j & 127;
    const int tid = threadIdx.x;
    float sm = 0.f, sq = 0.f;
    if (tid < 200) {
        const size_t base = ((size_t)h * 128 + f) * 200 + tid;
        for (int b0 = sl * 128; b0 < sl * 128 + 128; b0 += 8) {
            float v0 = g_z1[base + (size_t)(b0 + 0) * 102400];
            float v1 = g_z1[base + (size_t)(b0 + 1) * 102400];
            float v2 = g_z1[base + (size_t)(b0 + 2) * 102400];
            float v3 = g_z1[base + (size_t)(b0 + 3) * 102400];
            float v4 = g_z1[base + (size_t)(b0 + 4) * 102400];
            float v5 = g_z1[base + (size_t)(b0 + 5) * 102400];
            float v6 = g_z1[base + (size_t)(b0 + 6) * 102400];
            float v7 = g_z1[base + (size_t)(b0 + 7) * 102400];
            sm += ((v0 + v1) + (v2 + v3)) + ((v4 + v5) + (v6 + v7));
            sq += fmaf(v0, v0, fmaf(v1, v1, fmaf(v2, v2, v3 * v3)))
                + fmaf(v4, v4, fmaf(v5, v5, fmaf(v6, v6, v7 * v7)));
        }
    }
    __shared__ double rs[256], rq[256];
    rs[tid] = (double)sm; rq[tid] = (double)sq;
    __syncthreads();
    for (int o = 128; o > 0; o >>= 1) {
        if (tid < o) { rs[tid] += rs[tid + o]; rq[tid] += rq[tid + o]; }
        __syncthreads();
    }
    if (tid == 0) { g_p1[bid * 2] = rs[0]; g_p1[bid * 2 + 1] = rq[0]; }
}

__global__ void __launch_bounds__(512) kFin1()
{
    const int j = threadIdx.x;   // 512
    double sm = 0.0, sq = 0.0;
    for (int sl = 0; sl < 8; sl++) {
        sm += g_p1[(j * 8 + sl) * 2];
        sq += g_p1[(j * 8 + sl) * 2 + 1];
    }
    double N = 204800.0;
    double mean = sm / N;
    double var = sq / N - mean * mean;
    if (var < 0.0) var = 0.0;
    g_mean1[j] = (float)mean;
    g_istd1[j] = (float)(1.0 / sqrt(var + 1e-9));
}

__global__ void __launch_bounds__(256) kP2()
{
    const int bid = blockIdx.x;          // 2048 blocks
    const int j = bid >> 3, sl = bid & 7;
    const int h = j >> 6, f = j & 63;
    const int tid = threadIdx.x;
    float sm = 0.f, sq = 0.f;
    if (tid < 200) {
        const size_t base = ((size_t)h * 64 + f) * 200 + tid;
        for (int b0 = sl * 128; b0 < sl * 128 + 128; b0 += 8) {
            float v0 = g_z2[base + (size_t)(b0 + 0) * 51200];
            float v1 = g_z2[base + (size_t)(b0 + 1) * 51200];
            float v2 = g_z2[base + (size_t)(b0 + 2) * 51200];
            float v3 = g_z2[base + (size_t)(b0 + 3) * 51200];
            float v4 = g_z2[base + (size_t)(b0 + 4) * 51200];
            float v5 = g_z2[base + (size_t)(b0 + 5) * 51200];
            float v6 = g_z2[base + (size_t)(b0 + 6) * 51200];
            float v7 = g_z2[base + (size_t)(b0 + 7) * 51200];
            sm += ((v0 + v1) + (v2 + v3)) + ((v4 + v5) + (v6 + v7));
            sq += fmaf(v0, v0, fmaf(v1, v1, fmaf(v2, v2, v3 * v3)))
                + fmaf(v4, v4, fmaf(v5, v5, fmaf(v6, v6, v7 * v7)));
        }
    }
    __shared__ double rs[256], rq[256];
    rs[tid] = (double)sm; rq[tid] = (double)sq;
    __syncthreads();
    for (int o = 128; o > 0; o >>= 1) {
        if (tid < o) { rs[tid] += rs[tid + o]; rq[tid] += rq[tid + o]; }
        __syncthreads();
    }
    if (tid == 0) { g_p2[bid * 2] = rs[0]; g_p2[bid * 2 + 1] = rq[0]; }
}

__global__ void __launch_bounds__(256) kFin2()
{
    const int j = threadIdx.x;   // 256
    double sm = 0.0, sq = 0.0;
    for (int sl = 0; sl < 8; sl++) {
        sm += g_p2[(j * 8 + sl) * 2];
        sq += g_p2[(j * 8 + sl) * 2 + 1];
    }
    double N = 204800.0;
    double mean = sm / N;
    double var = sq / N - mean * mean;
    if (var < 0.0) var = 0.0;
    g_mean2[j] = (float)mean;
    g_istd2[j] = (float)(1.0 / sqrt(var + 1e-9));
}

// ---------------- kernel C: dice1 + mw2 GEMM, register-tiled 4t x 16g ----------------
// smem floats: ws 8192 | xs 6400 | mn 128 | isd 128 | al 128 | mbs 64  = 15040
constexpr int C_WS = 0;
constexpr int C_XS = 8192;
constexpr int C_MN = 14592;
constexpr int C_ISD = 14720;
constexpr int C_AL = 14848;
constexpr int C_MB = 14976;
constexpr int SMEM_C_BYTES = 15040 * 4;

__global__ void __launch_bounds__(256, 2) kC(
    const float* __restrict__ mw2, const float* __restrict__ mb2,
    const float* __restrict__ alpha1)
{
    extern __shared__ float smc[];
    float* ws  = smc + C_WS;    // [f][g] transposed mw2
    float* xs  = smc + C_XS;    // [f-sub 32][t 200] diced x tile
    float* mn  = smc + C_MN;
    float* isd = smc + C_ISD;
    float* al  = smc + C_AL;
    float* mbs = smc + C_MB;

    const int tid = threadIdx.x, bh = blockIdx.x;
    const int h = bh & 3;

    for (int i = tid; i < 8192; i += 256) {
        int f = i >> 6, g = i & 63;
        ws[i] = mw2[(size_t)h * 8192 + g * 128 + f];
    }
    if (tid < 128) {
        int j = h * 128 + tid;
        mn[tid] = g_mean1[j]; isd[tid] = g_istd1[j]; al[tid] = alpha1[j];
    } else if (tid < 192) {
        mbs[tid - 128] = mb2[h * 64 + (tid - 128)];
    }

    const bool act = tid < 200;
    const int t_tile = tid % 50, g_tile = tid / 50;
    const int t0 = t_tile * 4, gb = (g_tile < 4 ? g_tile : 0) * 16;

    u64 acc[4][8];
    #pragma unroll
    for (int t = 0; t < 4; t++)
        #pragma unroll
        for (int p = 0; p < 8; p++) acc[t][p] = 0ull;

    const float* zbase = g_z1 + (size_t)bh * 25600;

    for (int ft = 0; ft < 4; ft++) {
        __syncthreads();
        // stage 32 f-rows with dice applied (coalesced: each f-row is 200 contiguous)
        for (int i = tid; i < 6400; i += 256) {
            int f = i / 200, t = i - f * 200;
            int fg = ft * 32 + f;
            float zv = zbase[(size_t)fg * 200 + t];
            float xa = (zv - mn[fg]) * isd[fg];
            float p = __fdividef(1.f, 1.f + __expf(-xa));
            xs[i] = (p + al[fg] * (1.f - p)) * zv;
        }
        __syncthreads();
        if (act) {
            #pragma unroll 4
            for (int f = 0; f < 32; f++) {
                float4 xv = *(const float4*)&xs[f * 200 + t0];
                u64 xt[4];
                xt[0] = pack2(xv.x, xv.x); xt[1] = pack2(xv.y, xv.y);
                xt[2] = pack2(xv.z, xv.z); xt[3] = pack2(xv.w, xv.w);
                const float* wr = &ws[(ft * 32 + f) * 64 + gb];
                u64 wv[8];
                ld2x(wr,      wv[0], wv[1]);
                ld2x(wr + 4,  wv[2], wv[3]);
                ld2x(wr + 8,  wv[4], wv[5]);
                ld2x(wr + 12, wv[6], wv[7]);
                #pragma unroll
                for (int t = 0; t < 4; t++)
                    #pragma unroll
                    for (int p = 0; p < 8; p++)
                        acc[t][p] = fma2(xt[t], wv[p], acc[t][p]);
            }
        }
    }

    if (act) {
        float* op = g_z2 + (size_t)bh * 12800 + t0;
        #pragma unroll
        for (int p = 0; p < 8; p++) {
            float e0, o0, e1, o1, e2, o2, e3, o3;
            unpack2(acc[0][p], e0, o0); unpack2(acc[1][p], e1, o1);
            unpack2(acc[2][p], e2, o2); unpack2(acc[3][p], e3, o3);
            int ge = gb + 2 * p, go = ge + 1;
            float be = mbs[ge], bo = mbs[go];
            float4 ve = make_float4(e0 + be, e1 + be, e2 + be, e3 + be);
            float4 vo = make_float4(o0 + bo, o1 + bo, o2 + bo, o3 + bo);
            *(float4*)&op[(size_t)ge * 200] = ve;
            *(float4*)&op[(size_t)go * 200] = vo;
        }
    }
}

// ---------------- kernel E: dice2 + score + softmax + pooling ----------------
__global__ void __launch_bounds__(256) kE(
    const int* __restrict__ mask, const float* __restrict__ mw3,
    const float* __restrict__ mb3, const float* __restrict__ alpha2,
    float* __restrict__ out)
{
    __shared__ float w3s[64], m2s[64], i2s[64], a2s[64];
    __shared__ float red[256];
    __shared__ float wts[200];
    const int tid = threadIdx.x, bid = blockIdx.x;
    const int b = bid >> 2, h = bid & 3;
    if (tid < 64) {
        int j = h * 64 + tid;
        w3s[tid] = mw3[j]; m2s[tid] = g_mean2[j]; i2s[tid] = g_istd2[j]; a2s[tid] = alpha2[j];
    }
    __syncthreads();

    float sc = -3.0e38f;
    if (tid < 200) {
        const float* zp = g_z2 + (size_t)bid * 12800 + tid;
        float a = 0.f;
        #pragma unroll 4
        for (int g = 0; g < 64; g++) {
            float zv = zp[g * 200];
            float xa = (zv - m2s[g]) * i2s[g];
            float p = __fdividef(1.f, 1.f + __expf(-xa));
            float xv = (p + a2s[g] * (1.f - p)) * zv;
            a = fmaf(xv, w3s[g], a);
        }
        sc = a + mb3[h];
        if (mask[b * 200 + tid] == 0) sc = -1e9f;
    }
    red[tid] = sc;
    __syncthreads();
    for (int o = 128; o > 0; o >>= 1) {
        if (tid < o) red[tid] = fmaxf(red[tid], red[tid + o]);
        __syncthreads();
    }
    float mx = red[0];
    __syncthreads();
    float e = (tid < 200) ? __expf(sc - mx) : 0.f;
    red[tid] = e;
    __syncthreads();
    for (int o = 128; o > 0; o >>= 1) {
        if (tid < o) red[tid] += red[tid + o];
        __syncthreads();
    }
    float inv = 1.f / red[0];
    if (tid < 200) wts[tid] = e * inv;
    __syncthreads();

    const int c = tid >> 6, d = tid & 63;
    const float* hp = g_ho + (size_t)bid * 12800 + d * 200 + c * 50;
    float acc = 0.f;
    #pragma unroll 2
    for (int i = 0; i < 50; i++)
        acc = fmaf(wts[c * 50 + i], hp[i], acc);
    red[tid] = acc;
    __syncthreads();
    if (tid < 64)
        out[(size_t)bid * 64 + tid] = (red[tid] + red[tid + 64]) + (red[tid + 128] + red[tid + 192]);
}

// ---------------- launch ----------------
extern "C" void kernel_launch(void* const* d_in, const int* in_sizes, int n_in,
                              void* d_out, int out_size)
{
    const float* seq  = (const float*)d_in[0];
    const float* targ = (const float*)d_in[1];
    const int*   mask = (const int*)d_in[2];
    const float* Wqkv = (const float*)d_in[3];
    const float* Wo   = (const float*)d_in[4];
    const float* lng  = (const float*)d_in[5];
    const float* lnb  = (const float*)d_in[6];
    const float* fw1  = (const float*)d_in[7];
    const float* fb1  = (const float*)d_in[8];
    const float* fw2  = (const float*)d_in[9];
    const float* fb2  = (const float*)d_in[10];
    const float* mw1  = (const float*)d_in[11];
    const float* mb1  = (const float*)d_in[12];
    const float* a1   = (const float*)d_in[13];
    const float* mw2  = (const float*)d_in[14];
    const float* mb2  = (const float*)d_in[15];
    const float* a2   = (const float*)d_in[16];
    const float* mw3  = (const float*)d_in[17];
    const float* mb3  = (const float*)d_in[18];
    float* out = (float*)d_out;

    cudaFuncSetAttribute(kA, cudaFuncAttributeMaxDynamicSharedMemorySize, SMEM_A_BYTES);
    cudaFuncSetAttribute(kC, cudaFuncAttributeMaxDynamicSharedMemorySize, SMEM_C_BYTES);
    kA<<<4096, 224, SMEM_A_BYTES>>>(seq, targ, Wqkv, Wo, lng, lnb,
                                    fw1, fb1, fw2, fb2, mw1, mb1);
    kP1<<<4096, 256>>>();
    kFin1<<<1, 512>>>();
    kC<<<4096, 256, SMEM_C_BYTES>>>(mw2, mb2, a1);
    kP2<<<2048, 256>>>();
    kFin2<<<1, 256>>>();
    kE<<<4096, 256>>>(mask, mw3, mb3, a2, out);
}